// round 8
// baseline (speedup 1.0000x reference)
#include <cuda_runtime.h>
#include <cuda_bf16.h>
#include <mma.h>
#include <math.h>

using namespace nvcuda;

#define B_  2
#define S_  2048
#define D_  1024
#define H_  16
#define HD_ 64
#define KSEL 409
#define RANK0 (S_ - KSEL)   /* 1639: 0-indexed ascending rank of k-th largest */

#define MROWS (B_ * S_)     /* 4096 */

// ---------------- device scratch (no allocations allowed) ----------------
__device__ float g_Q[B_ * S_ * D_];   // [b,h,s,hd]
__device__ float g_K[B_ * S_ * D_];   // [b,h,s,hd]
__device__ float g_V[B_ * S_ * D_];   // [b,h,s,hd]
__device__ float g_A[B_ * S_ * D_];   // [b,s,d] attention output

// split-bf16 planes
__device__ __nv_bfloat16 g_X3[3][MROWS * D_];   // X split (also reused for nothing else)
__device__ __nv_bfloat16 g_A3[3][MROWS * D_];   // attention-out split
__device__ __nv_bfloat16 g_W3[3][D_ * D_];      // current weight split (reused, stream-ordered)

// ---------------- split3: a = b0 + b1 + b2 + O(2^-24 |a|) ----------------
__global__ __launch_bounds__(256) void split3_kernel(
    const float* __restrict__ src,
    __nv_bfloat16* __restrict__ d0, __nv_bfloat16* __restrict__ d1,
    __nv_bfloat16* __restrict__ d2, int n4)
{
    int i = blockIdx.x * 256 + threadIdx.x;
    if (i >= n4) return;
    float4 v = ((const float4*)src)[i];
    float va[4] = { v.x, v.y, v.z, v.w };
    unsigned short u0[4], u1[4], u2[4];
#pragma unroll
    for (int e = 0; e < 4; e++) {
        float r = va[e];
        __nv_bfloat16 b0 = __float2bfloat16(r);  r -= __bfloat162float(b0);
        __nv_bfloat16 b1 = __float2bfloat16(r);  r -= __bfloat162float(b1);
        __nv_bfloat16 b2 = __float2bfloat16(r);
        u0[e] = __bfloat16_as_ushort(b0);
        u1[e] = __bfloat16_as_ushort(b1);
        u2[e] = __bfloat16_as_ushort(b2);
    }
    uint2 w;
    w.x = (unsigned)u0[0] | ((unsigned)u0[1] << 16);
    w.y = (unsigned)u0[2] | ((unsigned)u0[3] << 16);
    ((uint2*)d0)[i] = w;
    w.x = (unsigned)u1[0] | ((unsigned)u1[1] << 16);
    w.y = (unsigned)u1[2] | ((unsigned)u1[3] << 16);
    ((uint2*)d1)[i] = w;
    w.x = (unsigned)u2[0] | ((unsigned)u2[1] << 16);
    w.y = (unsigned)u2[2] | ((unsigned)u2[3] << 16);
    ((uint2*)d2)[i] = w;
}

// ======== 3-split bf16 GEMM: C = A(MxK) @ W(NxK)^T + bias ========
// Operands pre-split into 3 bf16 planes each; 6 MMA products (sa+sb<=2)
// -> residual ~2^-26 |a||b| per term: fp32-class result everywhere.
#define GBM 128
#define GBN 128
#define GBK 32
#define GBKP 40            // bf16 smem row stride (80 B)
#define GSTG 36            // epilogue staging stride (floats)

// operands: 6 planes * 128*40 bf16 = 61440 B; epilogue stage 73728 B (union)
#define GEMM_SMEM_BYTES 73728

__global__ __launch_bounds__(256, 1) void gemm3_bt(
    const __nv_bfloat16* __restrict__ A0, const __nv_bfloat16* __restrict__ A1,
    const __nv_bfloat16* __restrict__ A2,
    const __nv_bfloat16* __restrict__ B0, const __nv_bfloat16* __restrict__ B1,
    const __nv_bfloat16* __restrict__ B2,
    const float* __restrict__ bias, float* __restrict__ C, int headLayout)
{
    extern __shared__ char gsm_raw[];
    __nv_bfloat16* sA = (__nv_bfloat16*)gsm_raw;      // [3][GBM*GBKP]
    __nv_bfloat16* sB = sA + 3 * GBM * GBKP;          // [3][GBN*GBKP]

    const __nv_bfloat16* Ap[3] = { A0, A1, A2 };
    const __nv_bfloat16* Bp[3] = { B0, B1, B2 };

    const int K = D_;
    int tid = threadIdx.x;
    int wid = tid >> 5;
    int wm = wid >> 2;         // 0..1
    int wn = wid & 3;          // 0..3
    int bm = blockIdx.y * GBM;
    int bn = blockIdx.x * GBN;

    wmma::fragment<wmma::accumulator, 16, 16, 16, float> fc[4][2];
#pragma unroll
    for (int i = 0; i < 4; i++)
#pragma unroll
        for (int j = 0; j < 2; j++) wmma::fill_fragment(fc[i][j], 0.0f);

    // load map per plane: linear = tid + it*256 -> row = linear/4, col8 = (linear%4)*8
    uint4 pa[3][2], pb[3][2];
#pragma unroll
    for (int p = 0; p < 3; p++)
#pragma unroll
        for (int it = 0; it < 2; it++) {
            int linear = tid + it * 256;
            int row = linear >> 2, col8 = (linear & 3) * 8;
            pa[p][it] = *(const uint4*)(Ap[p] + (size_t)(bm + row) * K + col8);
            pb[p][it] = *(const uint4*)(Bp[p] + (size_t)(bn + row) * K + col8);
        }

    const int NT = K / GBK;    // 32 k-tiles
    for (int t = 0; t < NT; t++) {
#pragma unroll
        for (int p = 0; p < 3; p++)
#pragma unroll
            for (int it = 0; it < 2; it++) {
                int linear = tid + it * 256;
                int row = linear >> 2, col8 = (linear & 3) * 8;
                *(uint4*)(sA + p * GBM * GBKP + row * GBKP + col8) = pa[p][it];
                *(uint4*)(sB + p * GBN * GBKP + row * GBKP + col8) = pb[p][it];
            }
        __syncthreads();

        if (t + 1 < NT) {
            int k0 = (t + 1) * GBK;
#pragma unroll
            for (int p = 0; p < 3; p++)
#pragma unroll
                for (int it = 0; it < 2; it++) {
                    int linear = tid + it * 256;
                    int row = linear >> 2, col8 = (linear & 3) * 8;
                    pa[p][it] = *(const uint4*)(Ap[p] + (size_t)(bm + row) * K + k0 + col8);
                    pb[p][it] = *(const uint4*)(Bp[p] + (size_t)(bn + row) * K + k0 + col8);
                }
        }

#pragma unroll
        for (int ks = 0; ks < GBK / 16; ks++) {
#pragma unroll
            for (int sa = 0; sa < 3; sa++) {
                wmma::fragment<wmma::matrix_a, 16, 16, 16, __nv_bfloat16, wmma::row_major> fa[4];
#pragma unroll
                for (int i = 0; i < 4; i++)
                    wmma::load_matrix_sync(fa[i],
                        sA + sa * GBM * GBKP + (wm * 64 + i * 16) * GBKP + ks * 16, GBKP);
#pragma unroll
                for (int sb = 0; sb < 3 - sa; sb++) {
                    wmma::fragment<wmma::matrix_b, 16, 16, 16, __nv_bfloat16, wmma::col_major> fb[2];
#pragma unroll
                    for (int j = 0; j < 2; j++)
                        wmma::load_matrix_sync(fb[j],
                            sB + sb * GBN * GBKP + (wn * 32 + j * 16) * GBKP + ks * 16, GBKP);
#pragma unroll
                    for (int i = 0; i < 4; i++)
#pragma unroll
                        for (int j = 0; j < 2; j++)
                            wmma::mma_sync(fc[i][j], fa[i], fb[j], fc[i][j]);
                }
            }
        }
        __syncthreads();
    }

    // ---- epilogue: stage per-warp tile in smem, write coalesced ----
    float* stage = (float*)gsm_raw + wid * 64 * GSTG;
#pragma unroll
    for (int i = 0; i < 4; i++)
#pragma unroll
        for (int j = 0; j < 2; j++)
            wmma::store_matrix_sync(stage + (i * 16) * GSTG + j * 16, fc[i][j],
                                    GSTG, wmma::mem_row_major);
    __syncwarp();

    int lane = tid & 31;
    for (int idx = lane; idx < 64 * 32; idx += 32) {
        int r = idx >> 5, c = idx & 31;
        int gr = bm + wm * 64 + r;
        int gc = bn + wn * 32 + c;
        float v = stage[r * GSTG + c] + bias[gc];
        if (headLayout) {
            int b = gr >> 11;
            int s = gr & (S_ - 1);
            int h = gc >> 6;
            int hd = gc & (HD_ - 1);
            C[(((size_t)(b * H_ + h)) * S_ + s) * HD_ + hd] = v;
        } else {
            C[(size_t)gr * D_ + gc] = v;
        }
    }
}

// ---------------- fused sparse attention (register-tiled) ----------------
#define QT    16        // query rows per block
#define CHUNK 128       // keys per chunk
#define NCH   (S_ / CHUNK)   // 16
#define SCP   2052      // padded score row stride
#define KVP2  68        // padded K/V/Q row stride

#define OFF_SC   0
#define OFF_KV   (QT * SCP)
#define OFF_QS   (OFF_KV + CHUNK * KVP2)
#define OFF_PB   (OFF_QS + QT * KVP2)
#define OFF_RCP  (OFF_PB + QT * KVP2)
#define OFF_HIST (OFF_RCP + 16)
#define SMEM_FLOATS (OFF_HIST + QT * 256)
#define SMEM_BYTES  (SMEM_FLOATS * 4)

__global__ __launch_bounds__(512, 1) void attn_kernel(
    const float* __restrict__ Q, const float* __restrict__ K,
    const float* __restrict__ V, float* __restrict__ O)
{
    extern __shared__ float sm[];
    float* sc    = sm + OFF_SC;
    float* kv    = sm + OFF_KV;
    float* qs    = sm + OFF_QS;
    float* pbuf  = sm + OFF_PB;
    float* s_rcp = sm + OFF_RCP;
    int*   hist  = (int*)(sm + OFF_HIST);

    int tid  = threadIdx.x;
    int lane = tid & 31;
    int w    = tid >> 5;
    int b    = blockIdx.z, h = blockIdx.y;
    int q0   = blockIdx.x * QT;
    size_t headBase = ((size_t)(b * H_ + h)) * S_ * HD_;
    const float* Qp = Q + headBase + (size_t)q0 * HD_;
    const float* Kp = K + headBase;
    const float* Vp = V + headBase;

    for (int i = tid; i < QT * HD_; i += 512) {
        int r = i >> 6, d = i & 63;
        qs[r * KVP2 + d] = Qp[r * HD_ + d] * 0.125f;
    }

    int qg = lane >> 3;
    int kl = lane & 7;
    {
        float4 pf[4];
#pragma unroll
        for (int it = 0; it < 4; it++) {
            int i = tid + it * 512;
            pf[it] = *(const float4*)(Kp + (size_t)(i >> 4) * HD_ + (i & 15) * 4);
        }
        for (int ch = 0; ch < NCH; ch++) {
#pragma unroll
            for (int it = 0; it < 4; it++) {
                int i = tid + it * 512;
                *(float4*)(kv + (i >> 4) * KVP2 + (i & 15) * 4) = pf[it];
            }
            __syncthreads();
            if (ch + 1 < NCH) {
#pragma unroll
                for (int it = 0; it < 4; it++) {
                    int i = tid + it * 512;
                    pf[it] = *(const float4*)(Kp +
                        (size_t)((ch + 1) * CHUNK + (i >> 4)) * HD_ + (i & 15) * 4);
                }
            }
            float acc0 = 0.f, acc1 = 0.f, acc2 = 0.f, acc3 = 0.f;
            const float* krow = kv + (w * 8 + kl) * KVP2;
#pragma unroll
            for (int d4 = 0; d4 < HD_; d4 += 4) {
                float4 kk  = *(const float4*)(krow + d4);
                float4 qv0 = *(const float4*)(qs + qg * KVP2 + d4);
                float4 qv1 = *(const float4*)(qs + (qg + 4) * KVP2 + d4);
                float4 qv2 = *(const float4*)(qs + (qg + 8) * KVP2 + d4);
                float4 qv3 = *(const float4*)(qs + (qg + 12) * KVP2 + d4);
                acc0 += qv0.x * kk.x + qv0.y * kk.y + qv0.z * kk.z + qv0.w * kk.w;
                acc1 += qv1.x * kk.x + qv1.y * kk.y + qv1.z * kk.z + qv1.w * kk.w;
                acc2 += qv2.x * kk.x + qv2.y * kk.y + qv2.z * kk.z + qv2.w * kk.w;
                acc3 += qv3.x * kk.x + qv3.y * kk.y + qv3.z * kk.z + qv3.w * kk.w;
            }
            int key = ch * CHUNK + w * 8 + kl;
            sc[ qg       * SCP + key] = acc0;
            sc[(qg + 4)  * SCP + key] = acc1;
            sc[(qg + 8)  * SCP + key] = acc2;
            sc[(qg + 12) * SCP + key] = acc3;
            __syncthreads();
        }
    }

    {
        unsigned pref = 0u; int rank = RANK0;
        const float* rowp = sc + w * SCP;
        int* hw = hist + w * 256;
        for (int pass = 0; pass < 4; pass++) {
            int shift = 24 - pass * 8;
#pragma unroll
            for (int j = lane; j < 256; j += 32) hw[j] = 0;
            __syncwarp();
            for (int i = lane; i < S_; i += 32) {
                unsigned bits = __float_as_uint(rowp[i]);
                unsigned u = (bits & 0x80000000u) ? ~bits : (bits | 0x80000000u);
                bool ok = (pass == 0) ||
                          ((u >> (shift + 8)) == (pref >> (shift + 8)));
                if (ok) atomicAdd(&hw[(u >> shift) & 255], 1);
            }
            __syncwarp();
            int c8[8]; int cnt = 0;
#pragma unroll
            for (int j = 0; j < 8; j++) { c8[j] = hw[lane * 8 + j]; cnt += c8[j]; }
            int inc = cnt;
#pragma unroll
            for (int off = 1; off < 32; off <<= 1) {
                int n = __shfl_up_sync(0xffffffffu, inc, off);
                if (lane >= off) inc += n;
            }
            int excl = inc - cnt;
            bool found = (rank >= excl) && (rank < inc);
            unsigned npref = pref; int nrank = rank;
            if (found) {
                int rr = rank - excl; int sel = -1;
#pragma unroll
                for (int j = 0; j < 8; j++) {
                    if (sel < 0) { if (rr < c8[j]) sel = j; else rr -= c8[j]; }
                }
                npref = pref | ((unsigned)(lane * 8 + sel) << shift);
                nrank = rr;
            }
            unsigned mask = __ballot_sync(0xffffffffu, found);
            int src = __ffs(mask) - 1;
            pref = __shfl_sync(0xffffffffu, npref, src);
            rank = __shfl_sync(0xffffffffu, nrank, src);
            __syncwarp();
        }
        unsigned tb = (pref & 0x80000000u) ? (pref ^ 0x80000000u) : ~pref;
        float thr = __uint_as_float(tb);

        float* rowm = sc + w * SCP;
        float m = -1e30f;
        for (int i = lane; i < S_; i += 32) m = fmaxf(m, rowm[i]);
#pragma unroll
        for (int off = 16; off; off >>= 1)
            m = fmaxf(m, __shfl_xor_sync(0xffffffffu, m, off));
        float l = 0.f;
        for (int i = lane; i < S_; i += 32) {
            float s = rowm[i];
            float p = (s >= thr) ? __expf(s - m) : 0.f;
            rowm[i] = p;
            l += p;
        }
#pragma unroll
        for (int off = 16; off; off >>= 1)
            l += __shfl_xor_sync(0xffffffffu, l, off);
        if (lane == 0) s_rcp[w] = 1.0f / l;
    }
    __syncthreads();

    {
        int dr = w & 7, kh = w >> 3;
        int qi = lane >> 1;
        int dcol = dr * 8 + (lane & 1) * 4;
        float4 acc = make_float4(0.f, 0.f, 0.f, 0.f);
        float4 pf[4];
#pragma unroll
        for (int it = 0; it < 4; it++) {
            int i = tid + it * 512;
            pf[it] = *(const float4*)(Vp + (size_t)(i >> 4) * HD_ + (i & 15) * 4);
        }
        for (int ch = 0; ch < NCH; ch++) {
#pragma unroll
            for (int it = 0; it < 4; it++) {
                int i = tid + it * 512;
                *(float4*)(kv + (i >> 4) * KVP2 + (i & 15) * 4) = pf[it];
            }
            __syncthreads();
            if (ch + 1 < NCH) {
#pragma unroll
                for (int it = 0; it < 4; it++) {
                    int i = tid + it * 512;
                    pf[it] = *(const float4*)(Vp +
                        (size_t)((ch + 1) * CHUNK + (i >> 4)) * HD_ + (i & 15) * 4);
                }
            }
            const float* prow  = sc + qi * SCP + ch * CHUNK + kh * 64;
            const float* vbase = kv + kh * 64 * KVP2 + dcol;
#pragma unroll
            for (int k4 = 0; k4 < 64; k4 += 4) {
                float4 p4 = *(const float4*)(prow + k4);
                float4 v0 = *(const float4*)(vbase + (k4 + 0) * KVP2);
                float4 v1 = *(const float4*)(vbase + (k4 + 1) * KVP2);
                float4 v2 = *(const float4*)(vbase + (k4 + 2) * KVP2);
                float4 v3 = *(const float4*)(vbase + (k4 + 3) * KVP2);
                acc.x += p4.x * v0.x; acc.y += p4.x * v0.y;
                acc.z += p4.x * v0.z; acc.w += p4.x * v0.w;
                acc.x += p4.y * v1.x; acc.y += p4.y * v1.y;
                acc.z += p4.y * v1.z; acc.w += p4.y * v1.w;
                acc.x += p4.z * v2.x; acc.y += p4.z * v2.y;
                acc.z += p4.z * v2.z; acc.w += p4.z * v2.w;
                acc.x += p4.w * v3.x; acc.y += p4.w * v3.y;
                acc.z += p4.w * v3.z; acc.w += p4.w * v3.w;
            }
            __syncthreads();
        }
        if (kh == 1) *(float4*)(pbuf + qi * KVP2 + dcol) = acc;
        __syncthreads();
        if (kh == 0) {
            float4 o2 = *(const float4*)(pbuf + qi * KVP2 + dcol);
            float rcp = s_rcp[qi];
            float4 r;
            r.x = (acc.x + o2.x) * rcp; r.y = (acc.y + o2.y) * rcp;
            r.z = (acc.z + o2.z) * rcp; r.w = (acc.w + o2.w) * rcp;
            float* op = O + ((size_t)b * S_ + q0 + qi) * D_ + h * HD_ + dcol;
            *(float4*)op = r;
        }
    }
}

// ---------------- launcher ----------------
extern "C" void kernel_launch(void* const* d_in, const int* in_sizes, int n_in,
                              void* d_out, int out_size)
{
    const float* X  = (const float*)d_in[0];
    const float* Wq = (const float*)d_in[1];
    const float* bq = (const float*)d_in[2];
    const float* Wk = (const float*)d_in[3];
    const float* bk = (const float*)d_in[4];
    const float* Wv = (const float*)d_in[5];
    const float* bv = (const float*)d_in[6];
    const float* Wo = (const float*)d_in[7];
    const float* bo = (const float*)d_in[8];

    static float *Qd = nullptr, *Kd = nullptr, *Vd = nullptr, *Ad = nullptr;
    static __nv_bfloat16 *X3[3], *A3[3], *W3[3];
    static bool init_done = false;
    if (!init_done) {
        cudaGetSymbolAddress((void**)&Qd, g_Q);
        cudaGetSymbolAddress((void**)&Kd, g_K);
        cudaGetSymbolAddress((void**)&Vd, g_V);
        cudaGetSymbolAddress((void**)&Ad, g_A);
        __nv_bfloat16* base;
        cudaGetSymbolAddress((void**)&base, g_X3);
        for (int p = 0; p < 3; p++) X3[p] = base + (size_t)p * MROWS * D_;
        cudaGetSymbolAddress((void**)&base, g_A3);
        for (int p = 0; p < 3; p++) A3[p] = base + (size_t)p * MROWS * D_;
        cudaGetSymbolAddress((void**)&base, g_W3);
        for (int p = 0; p < 3; p++) W3[p] = base + (size_t)p * D_ * D_;
        cudaFuncSetAttribute(attn_kernel,
                             cudaFuncAttributeMaxDynamicSharedMemorySize, SMEM_BYTES);
        cudaFuncSetAttribute(gemm3_bt,
                             cudaFuncAttributeMaxDynamicSharedMemorySize, GEMM_SMEM_BYTES);
        init_done = true;
    }

    const int NX4 = MROWS * D_ / 4;     // 1M
    const int NW4 = D_ * D_ / 4;        // 256K
    dim3 ggrid(D_ / GBN, MROWS / GBM);

    split3_kernel<<<NX4 / 256, 256>>>(X, X3[0], X3[1], X3[2], NX4);

    split3_kernel<<<NW4 / 256, 256>>>(Wq, W3[0], W3[1], W3[2], NW4);
    gemm3_bt<<<ggrid, 256, GEMM_SMEM_BYTES>>>(X3[0], X3[1], X3[2],
                                              W3[0], W3[1], W3[2], bq, Qd, 1);
    split3_kernel<<<NW4 / 256, 256>>>(Wk, W3[0], W3[1], W3[2], NW4);
    gemm3_bt<<<ggrid, 256, GEMM_SMEM_BYTES>>>(X3[0], X3[1], X3[2],
                                              W3[0], W3[1], W3[2], bk, Kd, 1);
    split3_kernel<<<NW4 / 256, 256>>>(Wv, W3[0], W3[1], W3[2], NW4);
    gemm3_bt<<<ggrid, 256, GEMM_SMEM_BYTES>>>(X3[0], X3[1], X3[2],
                                              W3[0], W3[1], W3[2], bv, Vd, 1);

    attn_kernel<<<dim3(S_ / QT, H_, B_), 512, SMEM_BYTES>>>(Qd, Kd, Vd, Ad);

    split3_kernel<<<NX4 / 256, 256>>>(Ad, A3[0], A3[1], A3[2], NX4);
    split3_kernel<<<NW4 / 256, 256>>>(Wo, W3[0], W3[1], W3[2], NW4);
    gemm3_bt<<<ggrid, 256, GEMM_SMEM_BYTES>>>(A3[0], A3[1], A3[2],
                                              W3[0], W3[1], W3[2], bo, (float*)d_out, 0);
}

// round 9
// speedup vs baseline: 1.0689x; 1.0689x over previous
#include <cuda_runtime.h>
#include <cuda_bf16.h>
#include <mma.h>
#include <math.h>

using namespace nvcuda;

#define B_  2
#define S_  2048
#define D_  1024
#define H_  16
#define HD_ 64
#define KSEL 409
#define RANK0 (S_ - KSEL)   /* 1639: 0-indexed ascending rank of k-th largest */

#define MROWS (B_ * S_)     /* 4096 */

// ---------------- device scratch (no allocations allowed) ----------------
__device__ float g_Q[B_ * S_ * D_];   // [b,h,s,hd]
__device__ float g_K[B_ * S_ * D_];   // [b,h,s,hd]
__device__ float g_V[B_ * S_ * D_];   // [b,h,s,hd]
__device__ float g_A[B_ * S_ * D_];   // [b,s,d] attention output

// split-bf16 planes
__device__ __nv_bfloat16 g_X3[3][MROWS * D_];
__device__ __nv_bfloat16 g_A3[2][MROWS * D_];   // A only needs 2 planes (V/O path)
__device__ __nv_bfloat16 g_W3[3][D_ * D_];      // current weight split (reused)

// ---------------- split3: a = b0 + b1 + b2 + O(2^-24 |a|) ----------------
__global__ __launch_bounds__(256) void split3_kernel(
    const float* __restrict__ src,
    __nv_bfloat16* __restrict__ d0, __nv_bfloat16* __restrict__ d1,
    __nv_bfloat16* __restrict__ d2, int n4)
{
    int i = blockIdx.x * 256 + threadIdx.x;
    if (i >= n4) return;
    float4 v = ((const float4*)src)[i];
    float va[4] = { v.x, v.y, v.z, v.w };
    unsigned short u0[4], u1[4], u2[4];
#pragma unroll
    for (int e = 0; e < 4; e++) {
        float r = va[e];
        __nv_bfloat16 b0 = __float2bfloat16(r);  r -= __bfloat162float(b0);
        __nv_bfloat16 b1 = __float2bfloat16(r);  r -= __bfloat162float(b1);
        __nv_bfloat16 b2 = __float2bfloat16(r);
        u0[e] = __bfloat16_as_ushort(b0);
        u1[e] = __bfloat16_as_ushort(b1);
        u2[e] = __bfloat16_as_ushort(b2);
    }
    uint2 w;
    w.x = (unsigned)u0[0] | ((unsigned)u0[1] << 16);
    w.y = (unsigned)u0[2] | ((unsigned)u0[3] << 16);
    ((uint2*)d0)[i] = w;
    w.x = (unsigned)u1[0] | ((unsigned)u1[1] << 16);
    w.y = (unsigned)u1[2] | ((unsigned)u1[3] << 16);
    ((uint2*)d1)[i] = w;
    if (d2) {
        w.x = (unsigned)u2[0] | ((unsigned)u2[1] << 16);
        w.y = (unsigned)u2[2] | ((unsigned)u2[3] << 16);
        ((uint2*)d2)[i] = w;
    }
}

// ======== pipelined split-bf16 GEMM: C = A(MxK) @ W(NxK)^T + bias ========
// cp.async double-buffered mainloop. PLANES=3 -> 6 products (sa+sb<=2),
// PLANES=2 -> 3 products (sa+sb<=1).
#define GBKP 40            // bf16 smem row stride (80 B, ldmatrix conflict-free)
#define GSTG 36            // epilogue staging stride (floats)
#define PLANE_SZ (128 * GBKP)

#define GEMM_SMEM_3 (2 * 3 * 2 * PLANE_SZ * 2)   // 122880 B
#define GEMM_SMEM_2 (2 * 2 * 2 * PLANE_SZ * 2)   // 81920 B

template<int PLANES>
__global__ __launch_bounds__(256, 1) void gemm_pipe(
    const __nv_bfloat16* __restrict__ A0, const __nv_bfloat16* __restrict__ A1,
    const __nv_bfloat16* __restrict__ A2,
    const __nv_bfloat16* __restrict__ B0, const __nv_bfloat16* __restrict__ B1,
    const __nv_bfloat16* __restrict__ B2,
    const float* __restrict__ bias, float* __restrict__ C, int headLayout)
{
    extern __shared__ char smraw[];
    __nv_bfloat16* sbase = (__nv_bfloat16*)smraw;
    const int STAGE_SZ = PLANES * 2 * PLANE_SZ;

    const __nv_bfloat16* Ap[3] = { A0, A1, A2 };
    const __nv_bfloat16* Bp[3] = { B0, B1, B2 };

    const int K = D_;
    int tid = threadIdx.x;
    int wid = tid >> 5;
    int wm = wid >> 2;         // 0..1
    int wn = wid & 3;          // 0..3
    int bm = blockIdx.y * 128;
    int bn = blockIdx.x * 128;

    wmma::fragment<wmma::accumulator, 16, 16, 16, float> fc[4][2];
#pragma unroll
    for (int i = 0; i < 4; i++)
#pragma unroll
        for (int j = 0; j < 2; j++) wmma::fill_fragment(fc[i][j], 0.0f);

    int chunk0 = tid;            // chunks 0..511 per matrix-plane, 2 iters
    int row0 = chunk0 >> 2;
    int col0 = (chunk0 & 3) * 8;
    int row1 = (chunk0 + 256) >> 2;
    int col1 = ((chunk0 + 256) & 3) * 8;

    auto load_stage = [&](int t, int buf) {
        int k0 = t * 32;
#pragma unroll
        for (int p = 0; p < PLANES; p++) {
            __nv_bfloat16* sA = sbase + buf * STAGE_SZ + p * PLANE_SZ;
            __nv_bfloat16* sB = sbase + buf * STAGE_SZ + (PLANES + p) * PLANE_SZ;
            {
                const __nv_bfloat16* ga = Ap[p] + (size_t)(bm + row0) * K + k0 + col0;
                const __nv_bfloat16* gb = Bp[p] + (size_t)(bn + row0) * K + k0 + col0;
                unsigned da = (unsigned)__cvta_generic_to_shared(sA + row0 * GBKP + col0);
                unsigned db = (unsigned)__cvta_generic_to_shared(sB + row0 * GBKP + col0);
                asm volatile("cp.async.cg.shared.global [%0], [%1], 16;" :: "r"(da), "l"(ga));
                asm volatile("cp.async.cg.shared.global [%0], [%1], 16;" :: "r"(db), "l"(gb));
            }
            {
                const __nv_bfloat16* ga = Ap[p] + (size_t)(bm + row1) * K + k0 + col1;
                const __nv_bfloat16* gb = Bp[p] + (size_t)(bn + row1) * K + k0 + col1;
                unsigned da = (unsigned)__cvta_generic_to_shared(sA + row1 * GBKP + col1);
                unsigned db = (unsigned)__cvta_generic_to_shared(sB + row1 * GBKP + col1);
                asm volatile("cp.async.cg.shared.global [%0], [%1], 16;" :: "r"(da), "l"(ga));
                asm volatile("cp.async.cg.shared.global [%0], [%1], 16;" :: "r"(db), "l"(gb));
            }
        }
        asm volatile("cp.async.commit_group;");
    };

    load_stage(0, 0);
    load_stage(1, 1);

    const int NT = K / 32;     // 32
    for (int t = 0; t < NT; t++) {
        if (t + 1 < NT)
            asm volatile("cp.async.wait_group 1;");
        else
            asm volatile("cp.async.wait_group 0;");
        __syncthreads();

        int buf = t & 1;
        __nv_bfloat16* stA = sbase + buf * STAGE_SZ;
        __nv_bfloat16* stB = stA + PLANES * PLANE_SZ;
#pragma unroll
        for (int ks = 0; ks < 2; ks++) {
            wmma::fragment<wmma::matrix_b, 16, 16, 16, __nv_bfloat16, wmma::col_major> fb[PLANES][2];
#pragma unroll
            for (int p = 0; p < PLANES; p++)
#pragma unroll
                for (int j = 0; j < 2; j++)
                    wmma::load_matrix_sync(fb[p][j],
                        stB + p * PLANE_SZ + (wn * 32 + j * 16) * GBKP + ks * 16, GBKP);
#pragma unroll
            for (int sa = 0; sa < PLANES; sa++) {
                wmma::fragment<wmma::matrix_a, 16, 16, 16, __nv_bfloat16, wmma::row_major> fa[4];
#pragma unroll
                for (int i = 0; i < 4; i++)
                    wmma::load_matrix_sync(fa[i],
                        stA + sa * PLANE_SZ + (wm * 64 + i * 16) * GBKP + ks * 16, GBKP);
#pragma unroll
                for (int sb = 0; sb < PLANES - sa; sb++)
#pragma unroll
                    for (int i = 0; i < 4; i++)
#pragma unroll
                        for (int j = 0; j < 2; j++)
                            wmma::mma_sync(fc[i][j], fa[i], fb[sb][j], fc[i][j]);
            }
        }
        __syncthreads();
        if (t + 2 < NT) load_stage(t + 2, buf);
    }

    // ---- epilogue: stage per-warp tile in smem (reuses operand smem) ----
    float* stage = (float*)smraw + wid * 64 * GSTG;
#pragma unroll
    for (int i = 0; i < 4; i++)
#pragma unroll
        for (int j = 0; j < 2; j++)
            wmma::store_matrix_sync(stage + (i * 16) * GSTG + j * 16, fc[i][j],
                                    GSTG, wmma::mem_row_major);
    __syncwarp();

    int lane = tid & 31;
    for (int idx = lane; idx < 64 * 32; idx += 32) {
        int r = idx >> 5, c = idx & 31;
        int gr = bm + wm * 64 + r;
        int gc = bn + wn * 32 + c;
        float v = stage[r * GSTG + c] + bias[gc];
        if (headLayout) {
            int b = gr >> 11;
            int s = gr & (S_ - 1);
            int h = gc >> 6;
            int hd = gc & (HD_ - 1);
            C[(((size_t)(b * H_ + h)) * S_ + s) * HD_ + hd] = v;
        } else {
            C[(size_t)gr * D_ + gc] = v;
        }
    }
}

// ---------------- fused sparse attention (register-tiled) ----------------
#define QT    16
#define CHUNK 128
#define NCH   (S_ / CHUNK)
#define SCP   2052
#define KVP2  68

#define OFF_SC   0
#define OFF_KV   (QT * SCP)
#define OFF_QS   (OFF_KV + CHUNK * KVP2)
#define OFF_PB   (OFF_QS + QT * KVP2)
#define OFF_RCP  (OFF_PB + QT * KVP2)
#define OFF_HIST (OFF_RCP + 16)
#define SMEM_FLOATS (OFF_HIST + QT * 256)
#define SMEM_BYTES  (SMEM_FLOATS * 4)

__global__ __launch_bounds__(512, 1) void attn_kernel(
    const float* __restrict__ Q, const float* __restrict__ K,
    const float* __restrict__ V, float* __restrict__ O)
{
    extern __shared__ float sm[];
    float* sc    = sm + OFF_SC;
    float* kv    = sm + OFF_KV;
    float* qs    = sm + OFF_QS;
    float* pbuf  = sm + OFF_PB;
    float* s_rcp = sm + OFF_RCP;
    int*   hist  = (int*)(sm + OFF_HIST);

    int tid  = threadIdx.x;
    int lane = tid & 31;
    int w    = tid >> 5;
    int b    = blockIdx.z, h = blockIdx.y;
    int q0   = blockIdx.x * QT;
    size_t headBase = ((size_t)(b * H_ + h)) * S_ * HD_;
    const float* Qp = Q + headBase + (size_t)q0 * HD_;
    const float* Kp = K + headBase;
    const float* Vp = V + headBase;

    for (int i = tid; i < QT * HD_; i += 512) {
        int r = i >> 6, d = i & 63;
        qs[r * KVP2 + d] = Qp[r * HD_ + d] * 0.125f;
    }

    int qg = lane >> 3;
    int kl = lane & 7;
    {
        float4 pf[4];
#pragma unroll
        for (int it = 0; it < 4; it++) {
            int i = tid + it * 512;
            pf[it] = *(const float4*)(Kp + (size_t)(i >> 4) * HD_ + (i & 15) * 4);
        }
        for (int ch = 0; ch < NCH; ch++) {
#pragma unroll
            for (int it = 0; it < 4; it++) {
                int i = tid + it * 512;
                *(float4*)(kv + (i >> 4) * KVP2 + (i & 15) * 4) = pf[it];
            }
            __syncthreads();
            if (ch + 1 < NCH) {
#pragma unroll
                for (int it = 0; it < 4; it++) {
                    int i = tid + it * 512;
                    pf[it] = *(const float4*)(Kp +
                        (size_t)((ch + 1) * CHUNK + (i >> 4)) * HD_ + (i & 15) * 4);
                }
            }
            float acc0 = 0.f, acc1 = 0.f, acc2 = 0.f, acc3 = 0.f;
            const float* krow = kv + (w * 8 + kl) * KVP2;
#pragma unroll
            for (int d4 = 0; d4 < HD_; d4 += 4) {
                float4 kk  = *(const float4*)(krow + d4);
                float4 qv0 = *(const float4*)(qs + qg * KVP2 + d4);
                float4 qv1 = *(const float4*)(qs + (qg + 4) * KVP2 + d4);
                float4 qv2 = *(const float4*)(qs + (qg + 8) * KVP2 + d4);
                float4 qv3 = *(const float4*)(qs + (qg + 12) * KVP2 + d4);
                acc0 += qv0.x * kk.x + qv0.y * kk.y + qv0.z * kk.z + qv0.w * kk.w;
                acc1 += qv1.x * kk.x + qv1.y * kk.y + qv1.z * kk.z + qv1.w * kk.w;
                acc2 += qv2.x * kk.x + qv2.y * kk.y + qv2.z * kk.z + qv2.w * kk.w;
                acc3 += qv3.x * kk.x + qv3.y * kk.y + qv3.z * kk.z + qv3.w * kk.w;
            }
            int key = ch * CHUNK + w * 8 + kl;
            sc[ qg       * SCP + key] = acc0;
            sc[(qg + 4)  * SCP + key] = acc1;
            sc[(qg + 8)  * SCP + key] = acc2;
            sc[(qg + 12) * SCP + key] = acc3;
            __syncthreads();
        }
    }

    {
        unsigned pref = 0u; int rank = RANK0;
        const float* rowp = sc + w * SCP;
        int* hw = hist + w * 256;
        for (int pass = 0; pass < 4; pass++) {
            int shift = 24 - pass * 8;
#pragma unroll
            for (int j = lane; j < 256; j += 32) hw[j] = 0;
            __syncwarp();
            for (int i = lane; i < S_; i += 32) {
                unsigned bits = __float_as_uint(rowp[i]);
                unsigned u = (bits & 0x80000000u) ? ~bits : (bits | 0x80000000u);
                bool ok = (pass == 0) ||
                          ((u >> (shift + 8)) == (pref >> (shift + 8)));
                if (ok) atomicAdd(&hw[(u >> shift) & 255], 1);
            }
            __syncwarp();
            int c8[8]; int cnt = 0;
#pragma unroll
            for (int j = 0; j < 8; j++) { c8[j] = hw[lane * 8 + j]; cnt += c8[j]; }
            int inc = cnt;
#pragma unroll
            for (int off = 1; off < 32; off <<= 1) {
                int n = __shfl_up_sync(0xffffffffu, inc, off);
                if (lane >= off) inc += n;
            }
            int excl = inc - cnt;
            bool found = (rank >= excl) && (rank < inc);
            unsigned npref = pref; int nrank = rank;
            if (found) {
                int rr = rank - excl; int sel = -1;
#pragma unroll
                for (int j = 0; j < 8; j++) {
                    if (sel < 0) { if (rr < c8[j]) sel = j; else rr -= c8[j]; }
                }
                npref = pref | ((unsigned)(lane * 8 + sel) << shift);
                nrank = rr;
            }
            unsigned mask = __ballot_sync(0xffffffffu, found);
            int src = __ffs(mask) - 1;
            pref = __shfl_sync(0xffffffffu, npref, src);
            rank = __shfl_sync(0xffffffffu, nrank, src);
            __syncwarp();
        }
        unsigned tb = (pref & 0x80000000u) ? (pref ^ 0x80000000u) : ~pref;
        float thr = __uint_as_float(tb);

        float* rowm = sc + w * SCP;
        float m = -1e30f;
        for (int i = lane; i < S_; i += 32) m = fmaxf(m, rowm[i]);
#pragma unroll
        for (int off = 16; off; off >>= 1)
            m = fmaxf(m, __shfl_xor_sync(0xffffffffu, m, off));
        float l = 0.f;
        for (int i = lane; i < S_; i += 32) {
            float s = rowm[i];
            float p = (s >= thr) ? __expf(s - m) : 0.f;
            rowm[i] = p;
            l += p;
        }
#pragma unroll
        for (int off = 16; off; off >>= 1)
            l += __shfl_xor_sync(0xffffffffu, l, off);
        if (lane == 0) s_rcp[w] = 1.0f / l;
    }
    __syncthreads();

    {
        int dr = w & 7, kh = w >> 3;
        int qi = lane >> 1;
        int dcol = dr * 8 + (lane & 1) * 4;
        float4 acc = make_float4(0.f, 0.f, 0.f, 0.f);
        float4 pf[4];
#pragma unroll
        for (int it = 0; it < 4; it++) {
            int i = tid + it * 512;
            pf[it] = *(const float4*)(Vp + (size_t)(i >> 4) * HD_ + (i & 15) * 4);
        }
        for (int ch = 0; ch < NCH; ch++) {
#pragma unroll
            for (int it = 0; it < 4; it++) {
                int i = tid + it * 512;
                *(float4*)(kv + (i >> 4) * KVP2 + (i & 15) * 4) = pf[it];
            }
            __syncthreads();
            if (ch + 1 < NCH) {
#pragma unroll
                for (int it = 0; it < 4; it++) {
                    int i = tid + it * 512;
                    pf[it] = *(const float4*)(Vp +
                        (size_t)((ch + 1) * CHUNK + (i >> 4)) * HD_ + (i & 15) * 4);
                }
            }
            const float* prow  = sc + qi * SCP + ch * CHUNK + kh * 64;
            const float* vbase = kv + kh * 64 * KVP2 + dcol;
#pragma unroll
            for (int k4 = 0; k4 < 64; k4 += 4) {
                float4 p4 = *(const float4*)(prow + k4);
                float4 v0 = *(const float4*)(vbase + (k4 + 0) * KVP2);
                float4 v1 = *(const float4*)(vbase + (k4 + 1) * KVP2);
                float4 v2 = *(const float4*)(vbase + (k4 + 2) * KVP2);
                float4 v3 = *(const float4*)(vbase + (k4 + 3) * KVP2);
                acc.x += p4.x * v0.x; acc.y += p4.x * v0.y;
                acc.z += p4.x * v0.z; acc.w += p4.x * v0.w;
                acc.x += p4.y * v1.x; acc.y += p4.y * v1.y;
                acc.z += p4.y * v1.z; acc.w += p4.y * v1.w;
                acc.x += p4.z * v2.x; acc.y += p4.z * v2.y;
                acc.z += p4.z * v2.z; acc.w += p4.z * v2.w;
                acc.x += p4.w * v3.x; acc.y += p4.w * v3.y;
                acc.z += p4.w * v3.z; acc.w += p4.w * v3.w;
            }
            __syncthreads();
        }
        if (kh == 1) *(float4*)(pbuf + qi * KVP2 + dcol) = acc;
        __syncthreads();
        if (kh == 0) {
            float4 o2 = *(const float4*)(pbuf + qi * KVP2 + dcol);
            float rcp = s_rcp[qi];
            float4 r;
            r.x = (acc.x + o2.x) * rcp; r.y = (acc.y + o2.y) * rcp;
            r.z = (acc.z + o2.z) * rcp; r.w = (acc.w + o2.w) * rcp;
            float* op = O + ((size_t)b * S_ + q0 + qi) * D_ + h * HD_ + dcol;
            *(float4*)op = r;
        }
    }
}

// ---------------- launcher ----------------
extern "C" void kernel_launch(void* const* d_in, const int* in_sizes, int n_in,
                              void* d_out, int out_size)
{
    const float* X  = (const float*)d_in[0];
    const float* Wq = (const float*)d_in[1];
    const float* bq = (const float*)d_in[2];
    const float* Wk = (const float*)d_in[3];
    const float* bk = (const float*)d_in[4];
    const float* Wv = (const float*)d_in[5];
    const float* bv = (const float*)d_in[6];
    const float* Wo = (const float*)d_in[7];
    const float* bo = (const float*)d_in[8];

    static float *Qd = nullptr, *Kd = nullptr, *Vd = nullptr, *Ad = nullptr;
    static __nv_bfloat16 *X3[3], *A3[2], *W3[3];
    static bool init_done = false;
    if (!init_done) {
        cudaGetSymbolAddress((void**)&Qd, g_Q);
        cudaGetSymbolAddress((void**)&Kd, g_K);
        cudaGetSymbolAddress((void**)&Vd, g_V);
        cudaGetSymbolAddress((void**)&Ad, g_A);
        __nv_bfloat16* base;
        cudaGetSymbolAddress((void**)&base, g_X3);
        for (int p = 0; p < 3; p++) X3[p] = base + (size_t)p * MROWS * D_;
        cudaGetSymbolAddress((void**)&base, g_A3);
        for (int p = 0; p < 2; p++) A3[p] = base + (size_t)p * MROWS * D_;
        cudaGetSymbolAddress((void**)&base, g_W3);
        for (int p = 0; p < 3; p++) W3[p] = base + (size_t)p * D_ * D_;
        cudaFuncSetAttribute(attn_kernel,
                             cudaFuncAttributeMaxDynamicSharedMemorySize, SMEM_BYTES);
        cudaFuncSetAttribute(gemm_pipe<3>,
                             cudaFuncAttributeMaxDynamicSharedMemorySize, GEMM_SMEM_3);
        cudaFuncSetAttribute(gemm_pipe<2>,
                             cudaFuncAttributeMaxDynamicSharedMemorySize, GEMM_SMEM_2);
        init_done = true;
    }

    const int NX4 = MROWS * D_ / 4;
    const int NW4 = D_ * D_ / 4;
    dim3 ggrid(D_ / 128, MROWS / 128);

    split3_kernel<<<NX4 / 256, 256>>>(X, X3[0], X3[1], X3[2], NX4);

    // Q, K: 3-plane / 6-product (threshold-sensitive path)
    split3_kernel<<<NW4 / 256, 256>>>(Wq, W3[0], W3[1], W3[2], NW4);
    gemm_pipe<3><<<ggrid, 256, GEMM_SMEM_3>>>(X3[0], X3[1], X3[2],
                                              W3[0], W3[1], W3[2], bq, Qd, 1);
    split3_kernel<<<NW4 / 256, 256>>>(Wk, W3[0], W3[1], W3[2], NW4);
    gemm_pipe<3><<<ggrid, 256, GEMM_SMEM_3>>>(X3[0], X3[1], X3[2],
                                              W3[0], W3[1], W3[2], bk, Kd, 1);

    // V: 2-plane / 3-product (linear-error path)
    split3_kernel<<<NW4 / 256, 256>>>(Wv, W3[0], W3[1], nullptr, NW4);
    gemm_pipe<2><<<ggrid, 256, GEMM_SMEM_2>>>(X3[0], X3[1], nullptr,
                                              W3[0], W3[1], nullptr, bv, Vd, 1);

    attn_kernel<<<dim3(S_ / QT, H_, B_), 512, SMEM_BYTES>>>(Qd, Kd, Vd, Ad);

    // O: 2-plane / 3-product
    split3_kernel<<<NX4 / 256, 256>>>(Ad, A3[0], A3[1], nullptr, NX4);
    split3_kernel<<<NW4 / 256, 256>>>(Wo, W3[0], W3[1], nullptr, NW4);
    gemm_pipe<2><<<ggrid, 256, GEMM_SMEM_2>>>(A3[0], A3[1], nullptr,
                                              W3[0], W3[1], nullptr, bo, (float*)d_out, 0);
}

// round 10
// speedup vs baseline: 1.2171x; 1.1387x over previous
#include <cuda_runtime.h>
#include <cuda_bf16.h>
#include <mma.h>
#include <math.h>

using namespace nvcuda;

#define B_  2
#define S_  2048
#define D_  1024
#define H_  16
#define HD_ 64
#define KSEL 409
#define RANK0 (S_ - KSEL)   /* 1639 */

#define MROWS (B_ * S_)     /* 4096 */

// ---------------- device scratch (no allocations allowed) ----------------
__device__ __align__(256) float g_Q[B_ * S_ * D_];   // [b,h,s,hd]
__device__ __align__(256) float g_K[B_ * S_ * D_];   // [b,h,s,hd]
__device__ __align__(256) float g_V[B_ * S_ * D_];   // [b,h,s,hd]
__device__ __align__(256) float g_A[B_ * S_ * D_];   // [b,s,d]

__device__ __align__(256) __nv_bfloat16 g_X3[3][MROWS * D_]; // X split -> later K split
__device__ __align__(256) __nv_bfloat16 g_A3[2][MROWS * D_]; // V split -> later A split
__device__ __align__(256) __nv_bfloat16 g_W3[3][D_ * D_];

// ---------------- split3 ----------------
__global__ __launch_bounds__(256) void split3_kernel(
    const float* __restrict__ src,
    __nv_bfloat16* __restrict__ d0, __nv_bfloat16* __restrict__ d1,
    __nv_bfloat16* __restrict__ d2, int n4)
{
    int i = blockIdx.x * 256 + threadIdx.x;
    if (i >= n4) return;
    float4 v = ((const float4*)src)[i];
    float va[4] = { v.x, v.y, v.z, v.w };
    unsigned short u0[4], u1[4], u2[4];
#pragma unroll
    for (int e = 0; e < 4; e++) {
        float r = va[e];
        __nv_bfloat16 b0 = __float2bfloat16(r);  r -= __bfloat162float(b0);
        __nv_bfloat16 b1 = __float2bfloat16(r);  r -= __bfloat162float(b1);
        __nv_bfloat16 b2 = __float2bfloat16(r);
        u0[e] = __bfloat16_as_ushort(b0);
        u1[e] = __bfloat16_as_ushort(b1);
        u2[e] = __bfloat16_as_ushort(b2);
    }
    uint2 w;
    w.x = (unsigned)u0[0] | ((unsigned)u0[1] << 16);
    w.y = (unsigned)u0[2] | ((unsigned)u0[3] << 16);
    ((uint2*)d0)[i] = w;
    w.x = (unsigned)u1[0] | ((unsigned)u1[1] << 16);
    w.y = (unsigned)u1[2] | ((unsigned)u1[3] << 16);
    ((uint2*)d1)[i] = w;
    if (d2) {
        w.x = (unsigned)u2[0] | ((unsigned)u2[1] << 16);
        w.y = (unsigned)u2[2] | ((unsigned)u2[3] << 16);
        ((uint2*)d2)[i] = w;
    }
}

// ======== pipelined split-bf16 GEMM (unchanged from R8) ========
#define GBKP 40
#define GSTG 36
#define PLANE_SZ (128 * GBKP)
#define GEMM_SMEM_3 (2 * 3 * 2 * PLANE_SZ * 2)
#define GEMM_SMEM_2 (2 * 2 * 2 * PLANE_SZ * 2)

template<int PLANES>
__global__ __launch_bounds__(256, 1) void gemm_pipe(
    const __nv_bfloat16* __restrict__ A0, const __nv_bfloat16* __restrict__ A1,
    const __nv_bfloat16* __restrict__ A2,
    const __nv_bfloat16* __restrict__ B0, const __nv_bfloat16* __restrict__ B1,
    const __nv_bfloat16* __restrict__ B2,
    const float* __restrict__ bias, float* __restrict__ C, int headLayout)
{
    extern __shared__ char smraw[];
    __nv_bfloat16* sbase = (__nv_bfloat16*)smraw;
    const int STAGE_SZ = PLANES * 2 * PLANE_SZ;
    const __nv_bfloat16* Ap[3] = { A0, A1, A2 };
    const __nv_bfloat16* Bp[3] = { B0, B1, B2 };

    const int K = D_;
    int tid = threadIdx.x;
    int wid = tid >> 5;
    int wm = wid >> 2;
    int wn = wid & 3;
    int bm = blockIdx.y * 128;
    int bn = blockIdx.x * 128;

    wmma::fragment<wmma::accumulator, 16, 16, 16, float> fc[4][2];
#pragma unroll
    for (int i = 0; i < 4; i++)
#pragma unroll
        for (int j = 0; j < 2; j++) wmma::fill_fragment(fc[i][j], 0.0f);

    int row0 = tid >> 2, col0 = (tid & 3) * 8;
    int row1 = (tid + 256) >> 2, col1 = ((tid + 256) & 3) * 8;

    auto load_stage = [&](int t, int buf) {
        int k0 = t * 32;
#pragma unroll
        for (int p = 0; p < PLANES; p++) {
            __nv_bfloat16* sA = sbase + buf * STAGE_SZ + p * PLANE_SZ;
            __nv_bfloat16* sB = sbase + buf * STAGE_SZ + (PLANES + p) * PLANE_SZ;
            {
                const __nv_bfloat16* ga = Ap[p] + (size_t)(bm + row0) * K + k0 + col0;
                const __nv_bfloat16* gb = Bp[p] + (size_t)(bn + row0) * K + k0 + col0;
                unsigned da = (unsigned)__cvta_generic_to_shared(sA + row0 * GBKP + col0);
                unsigned db = (unsigned)__cvta_generic_to_shared(sB + row0 * GBKP + col0);
                asm volatile("cp.async.cg.shared.global [%0], [%1], 16;" :: "r"(da), "l"(ga));
                asm volatile("cp.async.cg.shared.global [%0], [%1], 16;" :: "r"(db), "l"(gb));
            }
            {
                const __nv_bfloat16* ga = Ap[p] + (size_t)(bm + row1) * K + k0 + col1;
                const __nv_bfloat16* gb = Bp[p] + (size_t)(bn + row1) * K + k0 + col1;
                unsigned da = (unsigned)__cvta_generic_to_shared(sA + row1 * GBKP + col1);
                unsigned db = (unsigned)__cvta_generic_to_shared(sB + row1 * GBKP + col1);
                asm volatile("cp.async.cg.shared.global [%0], [%1], 16;" :: "r"(da), "l"(ga));
                asm volatile("cp.async.cg.shared.global [%0], [%1], 16;" :: "r"(db), "l"(gb));
            }
        }
        asm volatile("cp.async.commit_group;");
    };

    load_stage(0, 0);
    load_stage(1, 1);

    const int NT = K / 32;
    for (int t = 0; t < NT; t++) {
        if (t + 1 < NT) asm volatile("cp.async.wait_group 1;");
        else            asm volatile("cp.async.wait_group 0;");
        __syncthreads();

        int buf = t & 1;
        __nv_bfloat16* stA = sbase + buf * STAGE_SZ;
        __nv_bfloat16* stB = stA + PLANES * PLANE_SZ;
#pragma unroll
        for (int ks = 0; ks < 2; ks++) {
            wmma::fragment<wmma::matrix_b, 16, 16, 16, __nv_bfloat16, wmma::col_major> fb[PLANES][2];
#pragma unroll
            for (int p = 0; p < PLANES; p++)
#pragma unroll
                for (int j = 0; j < 2; j++)
                    wmma::load_matrix_sync(fb[p][j],
                        stB + p * PLANE_SZ + (wn * 32 + j * 16) * GBKP + ks * 16, GBKP);
#pragma unroll
            for (int sa = 0; sa < PLANES; sa++) {
                wmma::fragment<wmma::matrix_a, 16, 16, 16, __nv_bfloat16, wmma::row_major> fa[4];
#pragma unroll
                for (int i = 0; i < 4; i++)
                    wmma::load_matrix_sync(fa[i],
                        stA + sa * PLANE_SZ + (wm * 64 + i * 16) * GBKP + ks * 16, GBKP);
#pragma unroll
                for (int sb = 0; sb < PLANES - sa; sb++)
#pragma unroll
                    for (int i = 0; i < 4; i++)
#pragma unroll
                        for (int j = 0; j < 2; j++)
                            wmma::mma_sync(fc[i][j], fa[i], fb[sb][j], fc[i][j]);
            }
        }
        __syncthreads();
        if (t + 2 < NT) load_stage(t + 2, buf);
    }

    float* stage = (float*)smraw + wid * 64 * GSTG;
#pragma unroll
    for (int i = 0; i < 4; i++)
#pragma unroll
        for (int j = 0; j < 2; j++)
            wmma::store_matrix_sync(stage + (i * 16) * GSTG + j * 16, fc[i][j],
                                    GSTG, wmma::mem_row_major);
    __syncwarp();

    int lane = tid & 31;
    for (int idx = lane; idx < 64 * 32; idx += 32) {
        int r = idx >> 5, c = idx & 31;
        int gr = bm + wm * 64 + r;
        int gc = bn + wn * 32 + c;
        float v = stage[r * GSTG + c] + bias[gc];
        if (headLayout) {
            int b = gr >> 11;
            int s = gr & (S_ - 1);
            int h = gc >> 6;
            int hd = gc & (HD_ - 1);
            C[(((size_t)(b * H_ + h)) * S_ + s) * HD_ + hd] = v;
        } else {
            C[(size_t)gr * D_ + gc] = v;
        }
    }
}

// ======== tensor-core fused sparse attention ========
// 16 q-rows/block. QK^T: 3-split/6-product bf16 wmma. PV: 2-split/3-product.
#define SCP   2056                  /* score row stride (floats, 32B-mult) */
#define NCHUNK (S_ / 128)           /* 16 */
#define KTP   80                    /* K/V/Q tile row stride (bf16) */
#define PTP   144                   /* P tile row stride (bf16) */

#define AT_SC    0                           /* 16*2056*4   = 131584 */
#define AT_KV    131584                      /* 3*128*80*2  = 61440  */
#define AT_Q     193024                      /* 3*16*80*2   = 7680   */
#define AT_P     200704                      /* 2*16*144*2  = 9216   */
#define AT_HIST  209920                      /* 16*256*4    = 16384 (reused as PV staging) */
#define AT_RCP   226304                      /* 64 */
#define AT_SMEM  226368

__global__ __launch_bounds__(512, 1) void attn_tc(
    const float* __restrict__ Q,
    const __nv_bfloat16* __restrict__ K0, const __nv_bfloat16* __restrict__ K1,
    const __nv_bfloat16* __restrict__ K2,
    const __nv_bfloat16* __restrict__ V0, const __nv_bfloat16* __restrict__ V1,
    float* __restrict__ O)
{
    extern __shared__ char smem[];
    float* sc = (float*)(smem + AT_SC);
    __nv_bfloat16* kt = (__nv_bfloat16*)(smem + AT_KV);   // K tiles (3 planes) / V tiles (2)
    __nv_bfloat16* qt = (__nv_bfloat16*)(smem + AT_Q);
    __nv_bfloat16* pt = (__nv_bfloat16*)(smem + AT_P);
    int*   hist  = (int*)(smem + AT_HIST);
    float* stg   = (float*)(smem + AT_HIST);
    float* s_rcp = (float*)(smem + AT_RCP);

    int tid  = threadIdx.x;
    int lane = tid & 31;
    int w    = tid >> 5;            // 0..15
    int b    = blockIdx.z, h = blockIdx.y;
    int q0   = blockIdx.x * 16;
    size_t hb = ((size_t)(b * H_ + h)) * S_ * HD_;
    const __nv_bfloat16* Kp[3] = { K0 + hb, K1 + hb, K2 + hb };
    const __nv_bfloat16* Vp[2] = { V0 + hb, V1 + hb };

    // ---- phase A: load Q, scale by 1/8 (exact), 3-split into qt ----
    for (int i = tid; i < 16 * HD_; i += 512) {
        int r = i >> 6, d = i & 63;
        float v = Q[hb + (size_t)(q0 + r) * HD_ + d] * 0.125f;
        __nv_bfloat16 b0 = __float2bfloat16(v);  v -= __bfloat162float(b0);
        __nv_bfloat16 b1 = __float2bfloat16(v);  v -= __bfloat162float(b1);
        __nv_bfloat16 b2 = __float2bfloat16(v);
        qt[0 * 16 * KTP + r * KTP + d] = b0;
        qt[1 * 16 * KTP + r * KTP + d] = b1;
        qt[2 * 16 * KTP + r * KTP + d] = b2;
    }
    __syncthreads();

    // hoist Q fragments (warps 0..7 only use them)
    wmma::fragment<wmma::matrix_a, 16, 16, 16, __nv_bfloat16, wmma::row_major> fqa[3][4];
    if (w < 8) {
#pragma unroll
        for (int p = 0; p < 3; p++)
#pragma unroll
            for (int kk = 0; kk < 4; kk++)
                wmma::load_matrix_sync(fqa[p][kk], qt + p * 16 * KTP + kk * 16, KTP);
    }

    // ---- phase B: QK^T per 128-key chunk ----
    for (int ch = 0; ch < NCHUNK; ch++) {
        // load K chunk: 3 planes x 128 rows x 64 bf16 (8x16B per row)
#pragma unroll
        for (int it = 0; it < 6; it++) {
            int i = tid + it * 512;
            int plane = i >> 10;
            int rem = i & 1023;
            int row = rem >> 3, seg = rem & 7;
            const __nv_bfloat16* g = Kp[plane] + (size_t)(ch * 128 + row) * HD_ + seg * 8;
            unsigned d = (unsigned)__cvta_generic_to_shared(
                kt + plane * 128 * KTP + row * KTP + seg * 8);
            asm volatile("cp.async.cg.shared.global [%0], [%1], 16;" :: "r"(d), "l"(g));
        }
        asm volatile("cp.async.commit_group;");
        asm volatile("cp.async.wait_group 0;");
        __syncthreads();

        if (w < 8) {
            wmma::fragment<wmma::accumulator, 16, 16, 16, float> acc;
            wmma::fill_fragment(acc, 0.0f);
            const int SA[6] = {0, 0, 1, 1, 0, 2};
            const int SB[6] = {0, 1, 0, 1, 2, 0};
#pragma unroll
            for (int kk = 0; kk < 4; kk++) {
                wmma::fragment<wmma::matrix_b, 16, 16, 16, __nv_bfloat16, wmma::col_major> fkb[3];
#pragma unroll
                for (int p = 0; p < 3; p++)
                    wmma::load_matrix_sync(fkb[p],
                        kt + p * 128 * KTP + (w * 16) * KTP + kk * 16, KTP);
#pragma unroll
                for (int pr = 0; pr < 6; pr++)
                    wmma::mma_sync(acc, fqa[SA[pr]][kk], fkb[SB[pr]], acc);
            }
            wmma::store_matrix_sync(sc + ch * 128 + w * 16, acc, SCP, wmma::mem_row_major);
        }
        __syncthreads();   // kt reuse + score visibility
    }

    // ---- phase C: warp-private radix select (row w) + softmax ----
    {
        unsigned pref = 0u; int rank = RANK0;
        const float* rowp = sc + w * SCP;
        int* hw = hist + w * 256;
        for (int pass = 0; pass < 4; pass++) {
            int shift = 24 - pass * 8;
#pragma unroll
            for (int j = lane; j < 256; j += 32) hw[j] = 0;
            __syncwarp();
            for (int i = lane; i < S_; i += 32) {
                unsigned bits = __float_as_uint(rowp[i]);
                unsigned u = (bits & 0x80000000u) ? ~bits : (bits | 0x80000000u);
                bool ok = (pass == 0) ||
                          ((u >> (shift + 8)) == (pref >> (shift + 8)));
                if (ok) atomicAdd(&hw[(u >> shift) & 255], 1);
            }
            __syncwarp();
            int c8[8]; int cnt = 0;
#pragma unroll
            for (int j = 0; j < 8; j++) { c8[j] = hw[lane * 8 + j]; cnt += c8[j]; }
            int inc = cnt;
#pragma unroll
            for (int off = 1; off < 32; off <<= 1) {
                int n = __shfl_up_sync(0xffffffffu, inc, off);
                if (lane >= off) inc += n;
            }
            int excl = inc - cnt;
            bool found = (rank >= excl) && (rank < inc);
            unsigned npref = pref; int nrank = rank;
            if (found) {
                int rr = rank - excl; int sel = -1;
#pragma unroll
                for (int j = 0; j < 8; j++) {
                    if (sel < 0) { if (rr < c8[j]) sel = j; else rr -= c8[j]; }
                }
                npref = pref | ((unsigned)(lane * 8 + sel) << shift);
                nrank = rr;
            }
            unsigned mask = __ballot_sync(0xffffffffu, found);
            int src = __ffs(mask) - 1;
            pref = __shfl_sync(0xffffffffu, npref, src);
            rank = __shfl_sync(0xffffffffu, nrank, src);
            __syncwarp();
        }
        unsigned tb = (pref & 0x80000000u) ? (pref ^ 0x80000000u) : ~pref;
        float thr = __uint_as_float(tb);

        float* rowm = sc + w * SCP;
        float m = -1e30f;
        for (int i = lane; i < S_; i += 32) m = fmaxf(m, rowm[i]);
#pragma unroll
        for (int off = 16; off; off >>= 1)
            m = fmaxf(m, __shfl_xor_sync(0xffffffffu, m, off));
        float l = 0.f;
        for (int i = lane; i < S_; i += 32) {
            float s = rowm[i];
            float p = (s >= thr) ? __expf(s - m) : 0.f;
            rowm[i] = p;
            l += p;
        }
#pragma unroll
        for (int off = 16; off; off >>= 1)
            l += __shfl_xor_sync(0xffffffffu, l, off);
        if (lane == 0) s_rcp[w] = 1.0f / l;
    }
    __syncthreads();

    // ---- phase E: PV. accum persists across chunks ----
    int nt = w & 3;      // dim tile (16 dims)
    int kq = w >> 2;     // key quarter (2 ktiles of the chunk)
    wmma::fragment<wmma::accumulator, 16, 16, 16, float> facc;
    wmma::fill_fragment(facc, 0.0f);

    for (int ch = 0; ch < NCHUNK; ch++) {
        // load V chunk: 2 planes
#pragma unroll
        for (int it = 0; it < 4; it++) {
            int i = tid + it * 512;
            int plane = i >> 10;
            int rem = i & 1023;
            int row = rem >> 3, seg = rem & 7;
            const __nv_bfloat16* g = Vp[plane] + (size_t)(ch * 128 + row) * HD_ + seg * 8;
            unsigned d = (unsigned)__cvta_generic_to_shared(
                kt + plane * 128 * KTP + row * KTP + seg * 8);
            asm volatile("cp.async.cg.shared.global [%0], [%1], 16;" :: "r"(d), "l"(g));
        }
        asm volatile("cp.async.commit_group;");

        // convert P tile (probs -> 2-plane bf16)
#pragma unroll
        for (int it = 0; it < 4; it++) {
            int i = tid + it * 512;
            int r = i >> 7, k = i & 127;
            float p = sc[r * SCP + ch * 128 + k];
            __nv_bfloat16 b0 = __float2bfloat16(p);
            float rres = p - __bfloat162float(b0);
            __nv_bfloat16 b1 = __float2bfloat16(rres);
            pt[r * PTP + k] = b0;
            pt[16 * PTP + r * PTP + k] = b1;
        }
        asm volatile("cp.async.wait_group 0;");
        __syncthreads();

        // MMA: 2 ktiles for this warp, products (0,0),(0,1),(1,0)
#pragma unroll
        for (int t2 = 0; t2 < 2; t2++) {
            int kt2 = kq * 2 + t2;
            wmma::fragment<wmma::matrix_a, 16, 16, 16, __nv_bfloat16, wmma::row_major> pa0, pa1;
            wmma::fragment<wmma::matrix_b, 16, 16, 16, __nv_bfloat16, wmma::row_major> vb0, vb1;
            wmma::load_matrix_sync(pa0, pt + kt2 * 16, PTP);
            wmma::load_matrix_sync(pa1, pt + 16 * PTP + kt2 * 16, PTP);
            wmma::load_matrix_sync(vb0, kt + 0 * 128 * KTP + (kt2 * 16) * KTP + nt * 16, KTP);
            wmma::load_matrix_sync(vb1, kt + 1 * 128 * KTP + (kt2 * 16) * KTP + nt * 16, KTP);
            wmma::mma_sync(facc, pa0, vb0, facc);
            wmma::mma_sync(facc, pa0, vb1, facc);
            wmma::mma_sync(facc, pa1, vb0, facc);
        }
        __syncthreads();   // protect kt / pt for next chunk
    }

    // ---- reduce 4 key-quarters and write output ----
    wmma::store_matrix_sync(stg + w * 256, facc, 16, wmma::mem_row_major);
    __syncthreads();
    for (int i = tid; i < 16 * HD_; i += 512) {
        int r = i >> 6, d = i & 63;
        int nt2 = d >> 4, c = d & 15;
        float v = stg[(0 * 4 + nt2) * 256 + r * 16 + c]
                + stg[(1 * 4 + nt2) * 256 + r * 16 + c]
                + stg[(2 * 4 + nt2) * 256 + r * 16 + c]
                + stg[(3 * 4 + nt2) * 256 + r * 16 + c];
        v *= s_rcp[r];
        O[((size_t)b * S_ + q0 + r) * D_ + h * HD_ + d] = v;
    }
}

// ---------------- launcher ----------------
extern "C" void kernel_launch(void* const* d_in, const int* in_sizes, int n_in,
                              void* d_out, int out_size)
{
    const float* X  = (const float*)d_in[0];
    const float* Wq = (const float*)d_in[1];
    const float* bq = (const float*)d_in[2];
    const float* Wk = (const float*)d_in[3];
    const float* bk = (const float*)d_in[4];
    const float* Wv = (const float*)d_in[5];
    const float* bv = (const float*)d_in[6];
    const float* Wo = (const float*)d_in[7];
    const float* bo = (const float*)d_in[8];

    static float *Qd = nullptr, *Kd = nullptr, *Vd = nullptr, *Ad = nullptr;
    static __nv_bfloat16 *X3[3], *A3[2], *W3[3];
    static bool init_done = false;
    if (!init_done) {
        cudaGetSymbolAddress((void**)&Qd, g_Q);
        cudaGetSymbolAddress((void**)&Kd, g_K);
        cudaGetSymbolAddress((void**)&Vd, g_V);
        cudaGetSymbolAddress((void**)&Ad, g_A);
        __nv_bfloat16* base;
        cudaGetSymbolAddress((void**)&base, g_X3);
        for (int p = 0; p < 3; p++) X3[p] = base + (size_t)p * MROWS * D_;
        cudaGetSymbolAddress((void**)&base, g_A3);
        for (int p = 0; p < 2; p++) A3[p] = base + (size_t)p * MROWS * D_;
        cudaGetSymbolAddress((void**)&base, g_W3);
        for (int p = 0; p < 3; p++) W3[p] = base + (size_t)p * D_ * D_;
        cudaFuncSetAttribute(attn_tc,
                             cudaFuncAttributeMaxDynamicSharedMemorySize, AT_SMEM);
        cudaFuncSetAttribute(gemm_pipe<3>,
                             cudaFuncAttributeMaxDynamicSharedMemorySize, GEMM_SMEM_3);
        cudaFuncSetAttribute(gemm_pipe<2>,
                             cudaFuncAttributeMaxDynamicSharedMemorySize, GEMM_SMEM_2);
        init_done = true;
    }

    const int NX4 = MROWS * D_ / 4;
    const int NW4 = D_ * D_ / 4;
    dim3 ggrid(D_ / 128, MROWS / 128);

    split3_kernel<<<NX4 / 256, 256>>>(X, X3[0], X3[1], X3[2], NX4);

    split3_kernel<<<NW4 / 256, 256>>>(Wq, W3[0], W3[1], W3[2], NW4);
    gemm_pipe<3><<<ggrid, 256, GEMM_SMEM_3>>>(X3[0], X3[1], X3[2],
                                              W3[0], W3[1], W3[2], bq, Qd, 1);
    split3_kernel<<<NW4 / 256, 256>>>(Wk, W3[0], W3[1], W3[2], NW4);
    gemm_pipe<3><<<ggrid, 256, GEMM_SMEM_3>>>(X3[0], X3[1], X3[2],
                                              W3[0], W3[1], W3[2], bk, Kd, 1);
    split3_kernel<<<NW4 / 256, 256>>>(Wv, W3[0], W3[1], nullptr, NW4);
    gemm_pipe<2><<<ggrid, 256, GEMM_SMEM_2>>>(X3[0], X3[1], nullptr,
                                              W3[0], W3[1], nullptr, bv, Vd, 1);

    // K -> 3 bf16 planes (reuse X3; X no longer needed), V -> 2 planes (reuse A3)
    split3_kernel<<<NX4 / 256, 256>>>(Kd, X3[0], X3[1], X3[2], NX4);
    split3_kernel<<<NX4 / 256, 256>>>(Vd, A3[0], A3[1], nullptr, NX4);

    attn_tc<<<dim3(S_ / 16, H_, B_), 512, AT_SMEM>>>(
        Qd, X3[0], X3[1], X3[2], A3[0], A3[1], Ad);

    split3_kernel<<<NX4 / 256, 256>>>(Ad, A3[0], A3[1], nullptr, NX4);
    split3_kernel<<<NW4 / 256, 256>>>(Wo, W3[0], W3[1], nullptr, NW4);
    gemm_pipe<2><<<ggrid, 256, GEMM_SMEM_2>>>(A3[0], A3[1], nullptr,
                                              W3[0], W3[1], nullptr, bo, (float*)d_out, 0);
}

// round 11
// speedup vs baseline: 1.2570x; 1.0328x over previous
#include <cuda_runtime.h>
#include <cuda_bf16.h>
#include <mma.h>
#include <math.h>

using namespace nvcuda;

#define B_  2
#define S_  2048
#define D_  1024
#define H_  16
#define HD_ 64
#define KSEL 409
#define RANK0 (S_ - KSEL)   /* 1639 */
#define MROWS (B_ * S_)     /* 4096 */

// ---------------- device scratch ----------------
__device__ __align__(256) float g_Q[MROWS * D_];                 // [b,h,s,hd] fp32
__device__ __align__(256) __nv_bfloat16 g_K3[3][MROWS * D_];     // K planes [b,h,s,hd]
__device__ __align__(256) __nv_bfloat16 g_V2[2][MROWS * D_];     // V planes
__device__ __align__(256) __nv_bfloat16 g_X3[3][MROWS * D_];     // X planes
__device__ __align__(256) __nv_bfloat16 g_A3[2][MROWS * D_];     // attn-out planes [b,s,d]
__device__ __align__(256) __nv_bfloat16 g_W3[3][D_ * D_];        // weight planes

// ---------------- split3 ----------------
__global__ __launch_bounds__(256) void split3_kernel(
    const float* __restrict__ src,
    __nv_bfloat16* __restrict__ d0, __nv_bfloat16* __restrict__ d1,
    __nv_bfloat16* __restrict__ d2, int n4)
{
    int i = blockIdx.x * 256 + threadIdx.x;
    if (i >= n4) return;
    float4 v = ((const float4*)src)[i];
    float va[4] = { v.x, v.y, v.z, v.w };
    unsigned short u0[4], u1[4], u2[4];
#pragma unroll
    for (int e = 0; e < 4; e++) {
        float r = va[e];
        __nv_bfloat16 b0 = __float2bfloat16(r);  r -= __bfloat162float(b0);
        __nv_bfloat16 b1 = __float2bfloat16(r);  r -= __bfloat162float(b1);
        __nv_bfloat16 b2 = __float2bfloat16(r);
        u0[e] = __bfloat16_as_ushort(b0);
        u1[e] = __bfloat16_as_ushort(b1);
        u2[e] = __bfloat16_as_ushort(b2);
    }
    uint2 w;
    w.x = (unsigned)u0[0] | ((unsigned)u0[1] << 16);
    w.y = (unsigned)u0[2] | ((unsigned)u0[3] << 16);
    ((uint2*)d0)[i] = w;
    w.x = (unsigned)u1[0] | ((unsigned)u1[1] << 16);
    w.y = (unsigned)u1[2] | ((unsigned)u1[3] << 16);
    ((uint2*)d1)[i] = w;
    if (d2) {
        w.x = (unsigned)u2[0] | ((unsigned)u2[1] << 16);
        w.y = (unsigned)u2[2] | ((unsigned)u2[3] << 16);
        ((uint2*)d2)[i] = w;
    }
}

// ======== pipelined split-bf16 GEMM with fused split epilogue ========
// mode 0: fp32 C [M,D]; mode 1: fp32 head layout; mode 2: 3-plane bf16 head;
// mode 3: 2-plane bf16 head.
#define GBKP 40
#define GSTG 36
#define PLANE_SZ (128 * GBKP)
#define GEMM_SMEM_3 (2 * 3 * 2 * PLANE_SZ * 2)
#define GEMM_SMEM_2 (2 * 2 * 2 * PLANE_SZ * 2)

template<int PLANES>
__global__ __launch_bounds__(256, 1) void gemm_pipe(
    const __nv_bfloat16* __restrict__ A0, const __nv_bfloat16* __restrict__ A1,
    const __nv_bfloat16* __restrict__ A2,
    const __nv_bfloat16* __restrict__ B0, const __nv_bfloat16* __restrict__ B1,
    const __nv_bfloat16* __restrict__ B2,
    const float* __restrict__ bias, float* __restrict__ C,
    __nv_bfloat16* __restrict__ P0, __nv_bfloat16* __restrict__ P1,
    __nv_bfloat16* __restrict__ P2, int mode)
{
    extern __shared__ char smraw[];
    __nv_bfloat16* sbase = (__nv_bfloat16*)smraw;
    const int STAGE_SZ = PLANES * 2 * PLANE_SZ;
    const __nv_bfloat16* Ap[3] = { A0, A1, A2 };
    const __nv_bfloat16* Bp[3] = { B0, B1, B2 };

    const int K = D_;
    int tid = threadIdx.x;
    int wid = tid >> 5;
    int wm = wid >> 2;
    int wn = wid & 3;
    int bm = blockIdx.y * 128;
    int bn = blockIdx.x * 128;

    wmma::fragment<wmma::accumulator, 16, 16, 16, float> fc[4][2];
#pragma unroll
    for (int i = 0; i < 4; i++)
#pragma unroll
        for (int j = 0; j < 2; j++) wmma::fill_fragment(fc[i][j], 0.0f);

    int row0 = tid >> 2, col0 = (tid & 3) * 8;
    int row1 = (tid + 256) >> 2, col1 = ((tid + 256) & 3) * 8;

    auto load_stage = [&](int t, int buf) {
        int k0 = t * 32;
#pragma unroll
        for (int p = 0; p < PLANES; p++) {
            __nv_bfloat16* sA = sbase + buf * STAGE_SZ + p * PLANE_SZ;
            __nv_bfloat16* sB = sbase + buf * STAGE_SZ + (PLANES + p) * PLANE_SZ;
            {
                const __nv_bfloat16* ga = Ap[p] + (size_t)(bm + row0) * K + k0 + col0;
                const __nv_bfloat16* gb = Bp[p] + (size_t)(bn + row0) * K + k0 + col0;
                unsigned da = (unsigned)__cvta_generic_to_shared(sA + row0 * GBKP + col0);
                unsigned db = (unsigned)__cvta_generic_to_shared(sB + row0 * GBKP + col0);
                asm volatile("cp.async.cg.shared.global [%0], [%1], 16;" :: "r"(da), "l"(ga));
                asm volatile("cp.async.cg.shared.global [%0], [%1], 16;" :: "r"(db), "l"(gb));
            }
            {
                const __nv_bfloat16* ga = Ap[p] + (size_t)(bm + row1) * K + k0 + col1;
                const __nv_bfloat16* gb = Bp[p] + (size_t)(bn + row1) * K + k0 + col1;
                unsigned da = (unsigned)__cvta_generic_to_shared(sA + row1 * GBKP + col1);
                unsigned db = (unsigned)__cvta_generic_to_shared(sB + row1 * GBKP + col1);
                asm volatile("cp.async.cg.shared.global [%0], [%1], 16;" :: "r"(da), "l"(ga));
                asm volatile("cp.async.cg.shared.global [%0], [%1], 16;" :: "r"(db), "l"(gb));
            }
        }
        asm volatile("cp.async.commit_group;");
    };

    load_stage(0, 0);
    load_stage(1, 1);

    const int NT = K / 32;
    for (int t = 0; t < NT; t++) {
        if (t + 1 < NT) asm volatile("cp.async.wait_group 1;");
        else            asm volatile("cp.async.wait_group 0;");
        __syncthreads();

        int buf = t & 1;
        __nv_bfloat16* stA = sbase + buf * STAGE_SZ;
        __nv_bfloat16* stB = stA + PLANES * PLANE_SZ;
#pragma unroll
        for (int ks = 0; ks < 2; ks++) {
            wmma::fragment<wmma::matrix_b, 16, 16, 16, __nv_bfloat16, wmma::col_major> fb[PLANES][2];
#pragma unroll
            for (int p = 0; p < PLANES; p++)
#pragma unroll
                for (int j = 0; j < 2; j++)
                    wmma::load_matrix_sync(fb[p][j],
                        stB + p * PLANE_SZ + (wn * 32 + j * 16) * GBKP + ks * 16, GBKP);
#pragma unroll
            for (int sa = 0; sa < PLANES; sa++) {
                wmma::fragment<wmma::matrix_a, 16, 16, 16, __nv_bfloat16, wmma::row_major> fa[4];
#pragma unroll
                for (int i = 0; i < 4; i++)
                    wmma::load_matrix_sync(fa[i],
                        stA + sa * PLANE_SZ + (wm * 64 + i * 16) * GBKP + ks * 16, GBKP);
#pragma unroll
                for (int sb = 0; sb < PLANES - sa; sb++)
#pragma unroll
                    for (int i = 0; i < 4; i++)
#pragma unroll
                        for (int j = 0; j < 2; j++)
                            wmma::mma_sync(fc[i][j], fa[i], fb[sb][j], fc[i][j]);
            }
        }
        __syncthreads();
        if (t + 2 < NT) load_stage(t + 2, buf);
    }

    float* stage = (float*)smraw + wid * 64 * GSTG;
#pragma unroll
    for (int i = 0; i < 4; i++)
#pragma unroll
        for (int j = 0; j < 2; j++)
            wmma::store_matrix_sync(stage + (i * 16) * GSTG + j * 16, fc[i][j],
                                    GSTG, wmma::mem_row_major);
    __syncwarp();

    int lane = tid & 31;
    for (int idx = lane; idx < 64 * 32; idx += 32) {
        int r = idx >> 5, c = idx & 31;
        int gr = bm + wm * 64 + r;
        int gc = bn + wn * 32 + c;
        float v = stage[r * GSTG + c] + bias[gc];
        if (mode == 0) {
            C[(size_t)gr * D_ + gc] = v;
        } else {
            int b = gr >> 11;
            int s = gr & (S_ - 1);
            int h = gc >> 6;
            int hd = gc & (HD_ - 1);
            size_t oi = (((size_t)(b * H_ + h)) * S_ + s) * HD_ + hd;
            if (mode == 1) {
                C[oi] = v;
            } else {
                __nv_bfloat16 b0 = __float2bfloat16(v);
                float r1 = v - __bfloat162float(b0);
                __nv_bfloat16 b1 = __float2bfloat16(r1);
                P0[oi] = b0;
                P1[oi] = b1;
                if (mode == 2) P2[oi] = __float2bfloat16(r1 - __bfloat162float(b1));
            }
        }
    }
}

// ======== tensor-core fused sparse attention (pipelined) ========
#define SCP    2056                 /* score row stride (floats) */
#define CH64   64                   /* keys per chunk */
#define NCH64  (S_ / CH64)          /* 32 */
#define KTP    80                   /* K/V/Q/P tile row stride (bf16) */

#define AT_SC   0                                /* 16*2056*4 = 131584 */
#define AT_KV   131584                           /* 2 bufs*3planes*64*80*2 = 61440 */
#define AT_Q    (AT_KV + 61440)                  /* 3*16*80*2 = 7680 */
#define AT_P    (AT_Q + 7680)                    /* 2 bufs*2planes*16*80*2 = 10240 */
#define AT_STG  (AT_P + 10240)                   /* 16384 (stg/hist shared) */
#define AT_RCP  (AT_STG + 16384)                 /* 64 */
#define AT_SMEM (AT_RCP + 64)                    /* 227392 */

__global__ __launch_bounds__(512, 1) void attn_tc(
    const float* __restrict__ Q,
    const __nv_bfloat16* __restrict__ K0, const __nv_bfloat16* __restrict__ K1,
    const __nv_bfloat16* __restrict__ K2,
    const __nv_bfloat16* __restrict__ V0, const __nv_bfloat16* __restrict__ V1,
    __nv_bfloat16* __restrict__ A0, __nv_bfloat16* __restrict__ A1)
{
    extern __shared__ char smem[];
    float* sc = (float*)(smem + AT_SC);
    __nv_bfloat16* kb = (__nv_bfloat16*)(smem + AT_KV);   // K/V chunk buffers
    __nv_bfloat16* qt = (__nv_bfloat16*)(smem + AT_Q);
    __nv_bfloat16* pt = (__nv_bfloat16*)(smem + AT_P);
    float* stg   = (float*)(smem + AT_STG);
    int*   hist  = (int*)(smem + AT_STG);
    float* s_rcp = (float*)(smem + AT_RCP);

    const int KBUF = 3 * CH64 * KTP;     // K: one buffer = 3 planes
    const int VBUF = 2 * CH64 * KTP;     // V: one buffer = 2 planes
    const int PBUF = 2 * 16 * KTP;       // P: one buffer = 2 planes

    int tid  = threadIdx.x;
    int lane = tid & 31;
    int w    = tid >> 5;            // 0..15
    int b    = blockIdx.z, h = blockIdx.y;
    int q0   = blockIdx.x * 16;
    size_t hb = ((size_t)(b * H_ + h)) * S_ * HD_;
    const __nv_bfloat16* Kp[3] = { K0 + hb, K1 + hb, K2 + hb };
    const __nv_bfloat16* Vp[2] = { V0 + hb, V1 + hb };

    // ---- phase A: Q load, scale 1/8 (exact), 3-split ----
    for (int i = tid; i < 16 * HD_; i += 512) {
        int r = i >> 6, d = i & 63;
        float v = Q[hb + (size_t)(q0 + r) * HD_ + d] * 0.125f;
        __nv_bfloat16 b0 = __float2bfloat16(v);  v -= __bfloat162float(b0);
        __nv_bfloat16 b1 = __float2bfloat16(v);  v -= __bfloat162float(b1);
        __nv_bfloat16 b2 = __float2bfloat16(v);
        qt[0 * 16 * KTP + r * KTP + d] = b0;
        qt[1 * 16 * KTP + r * KTP + d] = b1;
        qt[2 * 16 * KTP + r * KTP + d] = b2;
    }
    __syncthreads();

    // warp roles for QK: nt = w&3 (16-key tile), kh = w>>2 (one kk slice)
    int nt = w & 3, kh = w >> 2;
    wmma::fragment<wmma::matrix_a, 16, 16, 16, __nv_bfloat16, wmma::row_major> fqa[3];
#pragma unroll
    for (int p = 0; p < 3; p++)
        wmma::load_matrix_sync(fqa[p], qt + p * 16 * KTP + kh * 16, KTP);

    auto load_k = [&](int ch) {
#pragma unroll
        for (int it = 0; it < 3; it++) {
            int i = tid + it * 512;
            int plane = i >> 9;
            int rem = i & 511;
            int row = rem >> 3, seg = rem & 7;
            const __nv_bfloat16* g = Kp[plane] + (size_t)(ch * CH64 + row) * HD_ + seg * 8;
            unsigned d = (unsigned)__cvta_generic_to_shared(
                kb + (ch & 1) * KBUF + plane * CH64 * KTP + row * KTP + seg * 8);
            asm volatile("cp.async.cg.shared.global [%0], [%1], 16;" :: "r"(d), "l"(g));
        }
        asm volatile("cp.async.commit_group;");
    };

    load_k(0);
    load_k(1);

    // ---- phase B: QK^T, 64-key chunks, double-buffered ----
    const int SA[6] = {0, 0, 1, 1, 0, 2};
    const int SB[6] = {0, 1, 0, 1, 2, 0};
    for (int ch = 0; ch < NCH64; ch++) {
        if (ch + 1 < NCH64) asm volatile("cp.async.wait_group 1;");
        else                asm volatile("cp.async.wait_group 0;");
        __syncthreads();

        __nv_bfloat16* kbuf = kb + (ch & 1) * KBUF;
        wmma::fragment<wmma::accumulator, 16, 16, 16, float> acc;
        wmma::fill_fragment(acc, 0.0f);
        {
            wmma::fragment<wmma::matrix_b, 16, 16, 16, __nv_bfloat16, wmma::col_major> fkb[3];
#pragma unroll
            for (int p = 0; p < 3; p++)
                wmma::load_matrix_sync(fkb[p],
                    kbuf + p * CH64 * KTP + (nt * 16) * KTP + kh * 16, KTP);
#pragma unroll
            for (int pr = 0; pr < 6; pr++)
                wmma::mma_sync(acc, fqa[SA[pr]], fkb[SB[pr]], acc);
        }
        if (kh > 0)
            wmma::store_matrix_sync(stg + (nt * 3 + kh - 1) * 256, acc, 16,
                                    wmma::mem_row_major);
        __syncthreads();
        if (kh == 0) {
            wmma::fragment<wmma::accumulator, 16, 16, 16, float> o;
#pragma unroll
            for (int s = 0; s < 3; s++) {
                wmma::load_matrix_sync(o, stg + (nt * 3 + s) * 256, 16,
                                       wmma::mem_row_major);
#pragma unroll
                for (int e = 0; e < acc.num_elements; e++) acc.x[e] += o.x[e];
            }
            wmma::store_matrix_sync(sc + ch * CH64 + nt * 16, acc, SCP,
                                    wmma::mem_row_major);
        }
        if (ch + 2 < NCH64) load_k(ch + 2);
    }
    __syncthreads();

    // ---- phase C: warp-private radix select (row w) + softmax ----
    {
        unsigned pref = 0u; int rank = RANK0;
        const float* rowp = sc + w * SCP;
        int* hw = hist + w * 256;
        for (int pass = 0; pass < 4; pass++) {
            int shift = 24 - pass * 8;
#pragma unroll
            for (int j = lane; j < 256; j += 32) hw[j] = 0;
            __syncwarp();
            for (int i = lane; i < S_; i += 32) {
                unsigned bits = __float_as_uint(rowp[i]);
                unsigned u = (bits & 0x80000000u) ? ~bits : (bits | 0x80000000u);
                bool ok = (pass == 0) ||
                          ((u >> (shift + 8)) == (pref >> (shift + 8)));
                if (ok) atomicAdd(&hw[(u >> shift) & 255], 1);
            }
            __syncwarp();
            int c8[8]; int cnt = 0;
#pragma unroll
            for (int j = 0; j < 8; j++) { c8[j] = hw[lane * 8 + j]; cnt += c8[j]; }
            int inc = cnt;
#pragma unroll
            for (int off = 1; off < 32; off <<= 1) {
                int n = __shfl_up_sync(0xffffffffu, inc, off);
                if (lane >= off) inc += n;
            }
            int excl = inc - cnt;
            bool found = (rank >= excl) && (rank < inc);
            unsigned npref = pref; int nrank = rank;
            if (found) {
                int rr = rank - excl; int sel = -1;
#pragma unroll
                for (int j = 0; j < 8; j++) {
                    if (sel < 0) { if (rr < c8[j]) sel = j; else rr -= c8[j]; }
                }
                npref = pref | ((unsigned)(lane * 8 + sel) << shift);
                nrank = rr;
            }
            unsigned mask = __ballot_sync(0xffffffffu, found);
            int src = __ffs(mask) - 1;
            pref = __shfl_sync(0xffffffffu, npref, src);
            rank = __shfl_sync(0xffffffffu, nrank, src);
            __syncwarp();
        }
        unsigned tb = (pref & 0x80000000u) ? (pref ^ 0x80000000u) : ~pref;
        float thr = __uint_as_float(tb);

        float* rowm = sc + w * SCP;
        float m = -1e30f;
        for (int i = lane; i < S_; i += 32) m = fmaxf(m, rowm[i]);
#pragma unroll
        for (int off = 16; off; off >>= 1)
            m = fmaxf(m, __shfl_xor_sync(0xffffffffu, m, off));
        float l = 0.f;
        for (int i = lane; i < S_; i += 32) {
            float s = rowm[i];
            float p = (s >= thr) ? __expf(s - m) : 0.f;
            rowm[i] = p;
            l += p;
        }
#pragma unroll
        for (int off = 16; off; off >>= 1)
            l += __shfl_xor_sync(0xffffffffu, l, off);
        if (lane == 0) s_rcp[w] = 1.0f / l;
    }
    __syncthreads();

    // ---- phase E: PV, 64-key chunks, double-buffered ----
    auto load_v = [&](int ch) {
#pragma unroll
        for (int it = 0; it < 2; it++) {
            int i = tid + it * 512;
            int plane = i >> 9;
            int rem = i & 511;
            int row = rem >> 3, seg = rem & 7;
            const __nv_bfloat16* g = Vp[plane] + (size_t)(ch * CH64 + row) * HD_ + seg * 8;
            unsigned d = (unsigned)__cvta_generic_to_shared(
                kb + (ch & 1) * VBUF + plane * CH64 * KTP + row * KTP + seg * 8);
            asm volatile("cp.async.cg.shared.global [%0], [%1], 16;" :: "r"(d), "l"(g));
        }
        asm volatile("cp.async.commit_group;");
    };
    auto conv_p = [&](int ch) {
        __nv_bfloat16* pb = pt + (ch & 1) * PBUF;
#pragma unroll
        for (int it = 0; it < 2; it++) {
            int i = tid + it * 512;
            int r = i >> 6, k = i & 63;
            float p = sc[r * SCP + ch * CH64 + k];
            __nv_bfloat16 b0 = __float2bfloat16(p);
            pb[r * KTP + k] = b0;
            pb[16 * KTP + r * KTP + k] = __float2bfloat16(p - __bfloat162float(b0));
        }
    };

    conv_p(0);
    load_v(0);
    load_v(1);

    // warp roles for PV: nt = dim tile (w&3), kq = key tile (w>>2)
    int kq = w >> 2;
    wmma::fragment<wmma::accumulator, 16, 16, 16, float> facc;
    wmma::fill_fragment(facc, 0.0f);

    for (int ch = 0; ch < NCH64; ch++) {
        if (ch + 1 < NCH64) asm volatile("cp.async.wait_group 1;");
        else                asm volatile("cp.async.wait_group 0;");
        __syncthreads();

        __nv_bfloat16* vbuf = kb + (ch & 1) * VBUF;
        __nv_bfloat16* pb   = pt + (ch & 1) * PBUF;
        {
            wmma::fragment<wmma::matrix_a, 16, 16, 16, __nv_bfloat16, wmma::row_major> pa0, pa1;
            wmma::fragment<wmma::matrix_b, 16, 16, 16, __nv_bfloat16, wmma::row_major> vb0, vb1;
            wmma::load_matrix_sync(pa0, pb + kq * 16, KTP);
            wmma::load_matrix_sync(pa1, pb + 16 * KTP + kq * 16, KTP);
            wmma::load_matrix_sync(vb0, vbuf + 0 * CH64 * KTP + (kq * 16) * KTP + nt * 16, KTP);
            wmma::load_matrix_sync(vb1, vbuf + 1 * CH64 * KTP + (kq * 16) * KTP + nt * 16, KTP);
            wmma::mma_sync(facc, pa0, vb0, facc);
            wmma::mma_sync(facc, pa0, vb1, facc);
            wmma::mma_sync(facc, pa1, vb0, facc);
        }
        if (ch + 1 < NCH64) conv_p(ch + 1);
        __syncthreads();
        if (ch + 2 < NCH64) load_v(ch + 2);
    }

    // ---- reduce 4 key-tiles, split, write A planes ----
    wmma::store_matrix_sync(stg + w * 256, facc, 16, wmma::mem_row_major);
    __syncthreads();
    for (int i = tid; i < 16 * HD_; i += 512) {
        int r = i >> 6, d = i & 63;
        int nt2 = d >> 4, c = d & 15;
        float v = stg[(0 * 4 + nt2) * 256 + r * 16 + c]
                + stg[(1 * 4 + nt2) * 256 + r * 16 + c]
                + stg[(2 * 4 + nt2) * 256 + r * 16 + c]
                + stg[(3 * 4 + nt2) * 256 + r * 16 + c];
        v *= s_rcp[r];
        size_t oi = ((size_t)b * S_ + q0 + r) * D_ + h * HD_ + d;
        __nv_bfloat16 b0 = __float2bfloat16(v);
        A0[oi] = b0;
        A1[oi] = __float2bfloat16(v - __bfloat162float(b0));
    }
}

// ---------------- launcher ----------------
extern "C" void kernel_launch(void* const* d_in, const int* in_sizes, int n_in,
                              void* d_out, int out_size)
{
    const float* X  = (const float*)d_in[0];
    const float* Wq = (const float*)d_in[1];
    const float* bq = (const float*)d_in[2];
    const float* Wk = (const float*)d_in[3];
    const float* bk = (const float*)d_in[4];
    const float* Wv = (const float*)d_in[5];
    const float* bv = (const float*)d_in[6];
    const float* Wo = (const float*)d_in[7];
    const float* bo = (const float*)d_in[8];

    static float *Qd = nullptr;
    static __nv_bfloat16 *X3[3], *K3[3], *V2[2], *A3[2], *W3[3];
    static bool init_done = false;
    if (!init_done) {
        cudaGetSymbolAddress((void**)&Qd, g_Q);
        __nv_bfloat16* base;
        cudaGetSymbolAddress((void**)&base, g_X3);
        for (int p = 0; p < 3; p++) X3[p] = base + (size_t)p * MROWS * D_;
        cudaGetSymbolAddress((void**)&base, g_K3);
        for (int p = 0; p < 3; p++) K3[p] = base + (size_t)p * MROWS * D_;
        cudaGetSymbolAddress((void**)&base, g_V2);
        for (int p = 0; p < 2; p++) V2[p] = base + (size_t)p * MROWS * D_;
        cudaGetSymbolAddress((void**)&base, g_A3);
        for (int p = 0; p < 2; p++) A3[p] = base + (size_t)p * MROWS * D_;
        cudaGetSymbolAddress((void**)&base, g_W3);
        for (int p = 0; p < 3; p++) W3[p] = base + (size_t)p * D_ * D_;
        cudaFuncSetAttribute(attn_tc,
                             cudaFuncAttributeMaxDynamicSharedMemorySize, AT_SMEM);
        cudaFuncSetAttribute(gemm_pipe<3>,
                             cudaFuncAttributeMaxDynamicSharedMemorySize, GEMM_SMEM_3);
        cudaFuncSetAttribute(gemm_pipe<2>,
                             cudaFuncAttributeMaxDynamicSharedMemorySize, GEMM_SMEM_2);
        init_done = true;
    }

    const int NX4 = MROWS * D_ / 4;
    const int NW4 = D_ * D_ / 4;
    dim3 ggrid(D_ / 128, MROWS / 128);

    split3_kernel<<<NX4 / 256, 256>>>(X, X3[0], X3[1], X3[2], NX4);

    // Q: fp32 head layout (mode 1)
    split3_kernel<<<NW4 / 256, 256>>>(Wq, W3[0], W3[1], W3[2], NW4);
    gemm_pipe<3><<<ggrid, 256, GEMM_SMEM_3>>>(X3[0], X3[1], X3[2],
        W3[0], W3[1], W3[2], bq, Qd, nullptr, nullptr, nullptr, 1);
    // K: 3-plane bf16 head layout (mode 2)
    split3_kernel<<<NW4 / 256, 256>>>(Wk, W3[0], W3[1], W3[2], NW4);
    gemm_pipe<3><<<ggrid, 256, GEMM_SMEM_3>>>(X3[0], X3[1], X3[2],
        W3[0], W3[1], W3[2], bk, nullptr, K3[0], K3[1], K3[2], 2);
    // V: 2-plane bf16 head layout (mode 3)
    split3_kernel<<<NW4 / 256, 256>>>(Wv, W3[0], W3[1], nullptr, NW4);
    gemm_pipe<2><<<ggrid, 256, GEMM_SMEM_2>>>(X3[0], X3[1], nullptr,
        W3[0], W3[1], nullptr, bv, nullptr, V2[0], V2[1], nullptr, 3);

    attn_tc<<<dim3(S_ / 16, H_, B_), 512, AT_SMEM>>>(
        Qd, K3[0], K3[1], K3[2], V2[0], V2[1], A3[0], A3[1]);

    // O: fp32 output (mode 0)
    split3_kernel<<<NW4 / 256, 256>>>(Wo, W3[0], W3[1], nullptr, NW4);
    gemm_pipe<2><<<ggrid, 256, GEMM_SMEM_2>>>(A3[0], A3[1], nullptr,
        W3[0], W3[1], nullptr, bo, (float*)d_out, nullptr, nullptr, nullptr, 0);
}

// round 12
// speedup vs baseline: 1.3002x; 1.0344x over previous
#include <cuda_runtime.h>
#include <cuda_bf16.h>
#include <mma.h>
#include <math.h>

using namespace nvcuda;

#define B_  2
#define S_  2048
#define D_  1024
#define H_  16
#define HD_ 64
#define KSEL 409
#define RANK0 (S_ - KSEL)   /* 1639 */
#define MROWS (B_ * S_)     /* 4096 */

// ---------------- device scratch ----------------
__device__ __align__(256) float g_Q[MROWS * D_];                 // [b,h,s,hd] fp32
__device__ __align__(256) __nv_bfloat16 g_K3[3][MROWS * D_];     // K planes [b,h,s,hd]
__device__ __align__(256) __nv_bfloat16 g_V2[2][MROWS * D_];     // V planes
__device__ __align__(256) __nv_bfloat16 g_X3[3][MROWS * D_];     // X planes
__device__ __align__(256) __nv_bfloat16 g_A3[2][MROWS * D_];     // attn-out planes [b,s,d]
__device__ __align__(256) __nv_bfloat16 g_W3[3][D_ * D_];        // weight planes

// ---------------- split3 ----------------
__global__ __launch_bounds__(256) void split3_kernel(
    const float* __restrict__ src,
    __nv_bfloat16* __restrict__ d0, __nv_bfloat16* __restrict__ d1,
    __nv_bfloat16* __restrict__ d2, int n4)
{
    int i = blockIdx.x * 256 + threadIdx.x;
    if (i >= n4) return;
    float4 v = ((const float4*)src)[i];
    float va[4] = { v.x, v.y, v.z, v.w };
    unsigned short u0[4], u1[4], u2[4];
#pragma unroll
    for (int e = 0; e < 4; e++) {
        float r = va[e];
        __nv_bfloat16 b0 = __float2bfloat16(r);  r -= __bfloat162float(b0);
        __nv_bfloat16 b1 = __float2bfloat16(r);  r -= __bfloat162float(b1);
        __nv_bfloat16 b2 = __float2bfloat16(r);
        u0[e] = __bfloat16_as_ushort(b0);
        u1[e] = __bfloat16_as_ushort(b1);
        u2[e] = __bfloat16_as_ushort(b2);
    }
    uint2 w;
    w.x = (unsigned)u0[0] | ((unsigned)u0[1] << 16);
    w.y = (unsigned)u0[2] | ((unsigned)u0[3] << 16);
    ((uint2*)d0)[i] = w;
    w.x = (unsigned)u1[0] | ((unsigned)u1[1] << 16);
    w.y = (unsigned)u1[2] | ((unsigned)u1[3] << 16);
    ((uint2*)d1)[i] = w;
    if (d2) {
        w.x = (unsigned)u2[0] | ((unsigned)u2[1] << 16);
        w.y = (unsigned)u2[2] | ((unsigned)u2[3] << 16);
        ((uint2*)d2)[i] = w;
    }
}

// ======== pipelined split-bf16 GEMM with fused split epilogue ========
// mode 0: fp32 C [M,D]; mode 1: fp32 head layout; mode 2: 3-plane bf16 head;
// mode 3: 2-plane bf16 head.
#define GBKP 40
#define GSTG 36
#define PLANE_SZ (128 * GBKP)
#define GEMM_SMEM_3 (2 * 3 * 2 * PLANE_SZ * 2)
#define GEMM_SMEM_2 (2 * 2 * 2 * PLANE_SZ * 2)

template<int PLANES>
__global__ __launch_bounds__(256, 1) void gemm_pipe(
    const __nv_bfloat16* __restrict__ A0, const __nv_bfloat16* __restrict__ A1,
    const __nv_bfloat16* __restrict__ A2,
    const __nv_bfloat16* __restrict__ B0, const __nv_bfloat16* __restrict__ B1,
    const __nv_bfloat16* __restrict__ B2,
    const float* __restrict__ bias, float* __restrict__ C,
    __nv_bfloat16* __restrict__ P0, __nv_bfloat16* __restrict__ P1,
    __nv_bfloat16* __restrict__ P2, int mode)
{
    extern __shared__ char smraw[];
    __nv_bfloat16* sbase = (__nv_bfloat16*)smraw;
    const int STAGE_SZ = PLANES * 2 * PLANE_SZ;
    const __nv_bfloat16* Ap[3] = { A0, A1, A2 };
    const __nv_bfloat16* Bp[3] = { B0, B1, B2 };

    const int K = D_;
    int tid = threadIdx.x;
    int wid = tid >> 5;
    int wm = wid >> 2;
    int wn = wid & 3;
    int bm = blockIdx.y * 128;
    int bn = blockIdx.x * 128;

    wmma::fragment<wmma::accumulator, 16, 16, 16, float> fc[4][2];
#pragma unroll
    for (int i = 0; i < 4; i++)
#pragma unroll
        for (int j = 0; j < 2; j++) wmma::fill_fragment(fc[i][j], 0.0f);

    int row0 = tid >> 2, col0 = (tid & 3) * 8;
    int row1 = (tid + 256) >> 2, col1 = ((tid + 256) & 3) * 8;

    auto load_stage = [&](int t, int buf) {
        int k0 = t * 32;
#pragma unroll
        for (int p = 0; p < PLANES; p++) {
            __nv_bfloat16* sA = sbase + buf * STAGE_SZ + p * PLANE_SZ;
            __nv_bfloat16* sB = sbase + buf * STAGE_SZ + (PLANES + p) * PLANE_SZ;
            {
                const __nv_bfloat16* ga = Ap[p] + (size_t)(bm + row0) * K + k0 + col0;
                const __nv_bfloat16* gb = Bp[p] + (size_t)(bn + row0) * K + k0 + col0;
                unsigned da = (unsigned)__cvta_generic_to_shared(sA + row0 * GBKP + col0);
                unsigned db = (unsigned)__cvta_generic_to_shared(sB + row0 * GBKP + col0);
                asm volatile("cp.async.cg.shared.global [%0], [%1], 16;" :: "r"(da), "l"(ga));
                asm volatile("cp.async.cg.shared.global [%0], [%1], 16;" :: "r"(db), "l"(gb));
            }
            {
                const __nv_bfloat16* ga = Ap[p] + (size_t)(bm + row1) * K + k0 + col1;
                const __nv_bfloat16* gb = Bp[p] + (size_t)(bn + row1) * K + k0 + col1;
                unsigned da = (unsigned)__cvta_generic_to_shared(sA + row1 * GBKP + col1);
                unsigned db = (unsigned)__cvta_generic_to_shared(sB + row1 * GBKP + col1);
                asm volatile("cp.async.cg.shared.global [%0], [%1], 16;" :: "r"(da), "l"(ga));
                asm volatile("cp.async.cg.shared.global [%0], [%1], 16;" :: "r"(db), "l"(gb));
            }
        }
        asm volatile("cp.async.commit_group;");
    };

    load_stage(0, 0);
    load_stage(1, 1);

    const int NT = K / 32;
    for (int t = 0; t < NT; t++) {
        if (t + 1 < NT) asm volatile("cp.async.wait_group 1;");
        else            asm volatile("cp.async.wait_group 0;");
        __syncthreads();

        int buf = t & 1;
        __nv_bfloat16* stA = sbase + buf * STAGE_SZ;
        __nv_bfloat16* stB = stA + PLANES * PLANE_SZ;
#pragma unroll
        for (int ks = 0; ks < 2; ks++) {
            wmma::fragment<wmma::matrix_b, 16, 16, 16, __nv_bfloat16, wmma::col_major> fb[PLANES][2];
#pragma unroll
            for (int p = 0; p < PLANES; p++)
#pragma unroll
                for (int j = 0; j < 2; j++)
                    wmma::load_matrix_sync(fb[p][j],
                        stB + p * PLANE_SZ + (wn * 32 + j * 16) * GBKP + ks * 16, GBKP);
#pragma unroll
            for (int sa = 0; sa < PLANES; sa++) {
                wmma::fragment<wmma::matrix_a, 16, 16, 16, __nv_bfloat16, wmma::row_major> fa[4];
#pragma unroll
                for (int i = 0; i < 4; i++)
                    wmma::load_matrix_sync(fa[i],
                        stA + sa * PLANE_SZ + (wm * 64 + i * 16) * GBKP + ks * 16, GBKP);
#pragma unroll
                for (int sb = 0; sb < PLANES - sa; sb++)
#pragma unroll
                    for (int i = 0; i < 4; i++)
#pragma unroll
                        for (int j = 0; j < 2; j++)
                            wmma::mma_sync(fc[i][j], fa[i], fb[sb][j], fc[i][j]);
            }
        }
        __syncthreads();
        if (t + 2 < NT) load_stage(t + 2, buf);
    }

    float* stage = (float*)smraw + wid * 64 * GSTG;
#pragma unroll
    for (int i = 0; i < 4; i++)
#pragma unroll
        for (int j = 0; j < 2; j++)
            wmma::store_matrix_sync(stage + (i * 16) * GSTG + j * 16, fc[i][j],
                                    GSTG, wmma::mem_row_major);
    __syncwarp();

    int lane = tid & 31;
    for (int idx = lane; idx < 64 * 32; idx += 32) {
        int r = idx >> 5, c = idx & 31;
        int gr = bm + wm * 64 + r;
        int gc = bn + wn * 32 + c;
        float v = stage[r * GSTG + c] + bias[gc];
        if (mode == 0) {
            C[(size_t)gr * D_ + gc] = v;
        } else {
            int b = gr >> 11;
            int s = gr & (S_ - 1);
            int h = gc >> 6;
            int hd = gc & (HD_ - 1);
            size_t oi = (((size_t)(b * H_ + h)) * S_ + s) * HD_ + hd;
            if (mode == 1) {
                C[oi] = v;
            } else {
                __nv_bfloat16 b0 = __float2bfloat16(v);
                float r1 = v - __bfloat162float(b0);
                __nv_bfloat16 b1 = __float2bfloat16(r1);
                P0[oi] = b0;
                P1[oi] = b1;
                if (mode == 2) P2[oi] = __float2bfloat16(r1 - __bfloat162float(b1));
            }
        }
    }
}

// ======== tensor-core fused sparse attention (pipelined, conflict-free KTP) ========
#define SCP    2056                 /* score row stride (floats) */
#define CH64   64                   /* keys per chunk */
#define NCH64  (S_ / CH64)          /* 32 */
#define KTP    72                   /* K/V/Q/P tile row stride (bf16): 144B = 36 words,
                                       8-row LDSM banks 0,4,8,...,28 -> conflict-free */

#define KBUF   (3 * CH64 * KTP)     /* 13824 bf16 = 27648 B */
#define VBUF   (2 * CH64 * KTP)     /* 9216 bf16 = 18432 B */
#define PBUF   (2 * 16 * KTP)       /* 2304 bf16 = 4608 B */

#define AT_SC   0                                /* 16*2056*4 = 131584 */
#define AT_KV   131584                           /* 2*KBUF*2 = 55296 */
#define AT_Q    (AT_KV + 55296)                  /* 3*16*72*2 = 6912 */
#define AT_P    (AT_Q + 6912)                    /* 2*PBUF*2 = 9216 */
#define AT_STG  (AT_P + 9216)                    /* 16384 (stg/hist shared) */
#define AT_RCP  (AT_STG + 16384)                 /* 64 */
#define AT_SMEM (AT_RCP + 64)                    /* 219456 */

__global__ __launch_bounds__(512, 1) void attn_tc(
    const float* __restrict__ Q,
    const __nv_bfloat16* __restrict__ K0, const __nv_bfloat16* __restrict__ K1,
    const __nv_bfloat16* __restrict__ K2,
    const __nv_bfloat16* __restrict__ V0, const __nv_bfloat16* __restrict__ V1,
    __nv_bfloat16* __restrict__ A0, __nv_bfloat16* __restrict__ A1)
{
    extern __shared__ char smem[];
    float* sc = (float*)(smem + AT_SC);
    __nv_bfloat16* kb = (__nv_bfloat16*)(smem + AT_KV);   // K/V chunk buffers
    __nv_bfloat16* qt = (__nv_bfloat16*)(smem + AT_Q);
    __nv_bfloat16* pt = (__nv_bfloat16*)(smem + AT_P);
    float* stg   = (float*)(smem + AT_STG);
    int*   hist  = (int*)(smem + AT_STG);
    float* s_rcp = (float*)(smem + AT_RCP);

    int tid  = threadIdx.x;
    int lane = tid & 31;
    int w    = tid >> 5;            // 0..15
    int b    = blockIdx.z, h = blockIdx.y;
    int q0   = blockIdx.x * 16;
    size_t hb = ((size_t)(b * H_ + h)) * S_ * HD_;
    const __nv_bfloat16* Kp[3] = { K0 + hb, K1 + hb, K2 + hb };
    const __nv_bfloat16* Vp[2] = { V0 + hb, V1 + hb };

    auto load_k = [&](int ch) {
#pragma unroll
        for (int it = 0; it < 3; it++) {
            int i = tid + it * 512;
            int plane = i >> 9;
            int rem = i & 511;
            int row = rem >> 3, seg = rem & 7;
            const __nv_bfloat16* g = Kp[plane] + (size_t)(ch * CH64 + row) * HD_ + seg * 8;
            unsigned d = (unsigned)__cvta_generic_to_shared(
                kb + (ch & 1) * KBUF + plane * CH64 * KTP + row * KTP + seg * 8);
            asm volatile("cp.async.cg.shared.global [%0], [%1], 16;" :: "r"(d), "l"(g));
        }
        asm volatile("cp.async.commit_group;");
    };
    auto load_v = [&](int ch) {
#pragma unroll
        for (int it = 0; it < 2; it++) {
            int i = tid + it * 512;
            int plane = i >> 9;
            int rem = i & 511;
            int row = rem >> 3, seg = rem & 7;
            const __nv_bfloat16* g = Vp[plane] + (size_t)(ch * CH64 + row) * HD_ + seg * 8;
            unsigned d = (unsigned)__cvta_generic_to_shared(
                kb + (ch & 1) * VBUF + plane * CH64 * KTP + row * KTP + seg * 8);
            asm volatile("cp.async.cg.shared.global [%0], [%1], 16;" :: "r"(d), "l"(g));
        }
        asm volatile("cp.async.commit_group;");
    };

    // kick off K chunk 0/1 loads immediately (overlap with Q split)
    load_k(0);
    load_k(1);

    // ---- phase A: Q load, scale 1/8 (exact), 3-split ----
    for (int i = tid; i < 16 * HD_; i += 512) {
        int r = i >> 6, d = i & 63;
        float v = Q[hb + (size_t)(q0 + r) * HD_ + d] * 0.125f;
        __nv_bfloat16 b0 = __float2bfloat16(v);  v -= __bfloat162float(b0);
        __nv_bfloat16 b1 = __float2bfloat16(v);  v -= __bfloat162float(b1);
        __nv_bfloat16 b2 = __float2bfloat16(v);
        qt[0 * 16 * KTP + r * KTP + d] = b0;
        qt[1 * 16 * KTP + r * KTP + d] = b1;
        qt[2 * 16 * KTP + r * KTP + d] = b2;
    }
    __syncthreads();

    // warp roles for QK: nt = w&3 (16-key tile), kh = w>>2 (one kk slice)
    int nt = w & 3, kh = w >> 2;
    wmma::fragment<wmma::matrix_a, 16, 16, 16, __nv_bfloat16, wmma::row_major> fqa[3];
#pragma unroll
    for (int p = 0; p < 3; p++)
        wmma::load_matrix_sync(fqa[p], qt + p * 16 * KTP + kh * 16, KTP);

    // ---- phase B: QK^T, 64-key chunks, double-buffered ----
    const int SA[6] = {0, 0, 1, 1, 0, 2};
    const int SB[6] = {0, 1, 0, 1, 2, 0};
    for (int ch = 0; ch < NCH64; ch++) {
        if (ch + 1 < NCH64) asm volatile("cp.async.wait_group 1;");
        else                asm volatile("cp.async.wait_group 0;");
        __syncthreads();

        __nv_bfloat16* kbuf = kb + (ch & 1) * KBUF;
        wmma::fragment<wmma::accumulator, 16, 16, 16, float> acc;
        wmma::fill_fragment(acc, 0.0f);
        {
            wmma::fragment<wmma::matrix_b, 16, 16, 16, __nv_bfloat16, wmma::col_major> fkb[3];
#pragma unroll
            for (int p = 0; p < 3; p++)
                wmma::load_matrix_sync(fkb[p],
                    kbuf + p * CH64 * KTP + (nt * 16) * KTP + kh * 16, KTP);
#pragma unroll
            for (int pr = 0; pr < 6; pr++)
                wmma::mma_sync(acc, fqa[SA[pr]], fkb[SB[pr]], acc);
        }
        if (kh > 0)
            wmma::store_matrix_sync(stg + (nt * 3 + kh - 1) * 256, acc, 16,
                                    wmma::mem_row_major);
        __syncthreads();
        if (kh == 0) {
            wmma::fragment<wmma::accumulator, 16, 16, 16, float> o;
#pragma unroll
            for (int s = 0; s < 3; s++) {
                wmma::load_matrix_sync(o, stg + (nt * 3 + s) * 256, 16,
                                       wmma::mem_row_major);
#pragma unroll
                for (int e = 0; e < acc.num_elements; e++) acc.x[e] += o.x[e];
            }
            wmma::store_matrix_sync(sc + ch * CH64 + nt * 16, acc, SCP,
                                    wmma::mem_row_major);
        }
        if (ch + 2 < NCH64) load_k(ch + 2);
    }
    __syncthreads();

    // kick off V chunk 0/1 loads now — hidden behind phase C (kb is free)
    load_v(0);
    load_v(1);

    // ---- phase C: warp-private radix select (row w) + softmax ----
    {
        unsigned pref = 0u; int rank = RANK0;
        const float* rowp = sc + w * SCP;
        int* hw = hist + w * 256;
        for (int pass = 0; pass < 4; pass++) {
            int shift = 24 - pass * 8;
#pragma unroll
            for (int j = lane; j < 256; j += 32) hw[j] = 0;
            __syncwarp();
            for (int i = lane; i < S_; i += 32) {
                unsigned bits = __float_as_uint(rowp[i]);
                unsigned u = (bits & 0x80000000u) ? ~bits : (bits | 0x80000000u);
                bool ok = (pass == 0) ||
                          ((u >> (shift + 8)) == (pref >> (shift + 8)));
                if (ok) atomicAdd(&hw[(u >> shift) & 255], 1);
            }
            __syncwarp();
            int c8[8]; int cnt = 0;
#pragma unroll
            for (int j = 0; j < 8; j++) { c8[j] = hw[lane * 8 + j]; cnt += c8[j]; }
            int inc = cnt;
#pragma unroll
            for (int off = 1; off < 32; off <<= 1) {
                int n = __shfl_up_sync(0xffffffffu, inc, off);
                if (lane >= off) inc += n;
            }
            int excl = inc - cnt;
            bool found = (rank >= excl) && (rank < inc);
            unsigned npref = pref; int nrank = rank;
            if (found) {
                int rr = rank - excl; int sel = -1;
#pragma unroll
                for (int j = 0; j < 8; j++) {
                    if (sel < 0) { if (rr < c8[j]) sel = j; else rr -= c8[j]; }
                }
                npref = pref | ((unsigned)(lane * 8 + sel) << shift);
                nrank = rr;
            }
            unsigned mask = __ballot_sync(0xffffffffu, found);
            int src = __ffs(mask) - 1;
            pref = __shfl_sync(0xffffffffu, npref, src);
            rank = __shfl_sync(0xffffffffu, nrank, src);
            __syncwarp();
        }
        unsigned tb = (pref & 0x80000000u) ? (pref ^ 0x80000000u) : ~pref;
        float thr = __uint_as_float(tb);

        float* rowm = sc + w * SCP;
        float m = -1e30f;
        for (int i = lane; i < S_; i += 32) m = fmaxf(m, rowm[i]);
#pragma unroll
        for (int off = 16; off; off >>= 1)
            m = fmaxf(m, __shfl_xor_sync(0xffffffffu, m, off));
        float l = 0.f;
        for (int i = lane; i < S_; i += 32) {
            float s = rowm[i];
            float p = (s >= thr) ? __expf(s - m) : 0.f;
            rowm[i] = p;
            l += p;
        }
#pragma unroll
        for (int off = 16; off; off >>= 1)
            l += __shfl_xor_sync(0xffffffffu, l, off);
        if (lane == 0) s_rcp[w] = 1.0f / l;
    }
    __syncthreads();

    // ---- phase E: PV, 64-key chunks, double-buffered ----
    auto conv_p = [&](int ch) {
        __nv_bfloat16* pb = pt + (ch & 1) * PBUF;
#pragma unroll
        for (int it = 0; it < 2; it++) {
            int i = tid + it * 512;
            int r = i >> 6, k = i & 63;
            float p = sc[r * SCP + ch * CH64 + k];
            __nv_bfloat16 b0 = __float2bfloat16(p);
            pb[r * KTP + k] = b0;
            pb[16 * KTP + r * KTP + k] = __float2bfloat16(p - __bfloat162float(b0));
        }
    };

    conv_p(0);

    // warp roles for PV: nt = dim tile (w&3), kq = key tile (w>>2)
    int kq = w >> 2;
    wmma::fragment<wmma::accumulator, 16, 16, 16, float> facc;
    wmma::fill_fragment(facc, 0.0f);

    for (int ch = 0; ch < NCH64; ch++) {
        if (ch + 1 < NCH64) asm volatile("cp.async.wait_group 1;");
        else                asm volatile("cp.async.wait_group 0;");
        __syncthreads();

        __nv_bfloat16* vbuf = kb + (ch & 1) * VBUF;
        __nv_bfloat16* pb   = pt + (ch & 1) * PBUF;
        {
            wmma::fragment<wmma::matrix_a, 16, 16, 16, __nv_bfloat16, wmma::row_major> pa0, pa1;
            wmma::fragment<wmma::matrix_b, 16, 16, 16, __nv_bfloat16, wmma::row_major> vb0, vb1;
            wmma::load_matrix_sync(pa0, pb + kq * 16, KTP);
            wmma::load_matrix_sync(pa1, pb + 16 * KTP + kq * 16, KTP);
            wmma::load_matrix_sync(vb0, vbuf + 0 * CH64 * KTP + (kq * 16) * KTP + nt * 16, KTP);
            wmma::load_matrix_sync(vb1, vbuf + 1 * CH64 * KTP + (kq * 16) * KTP + nt * 16, KTP);
            wmma::mma_sync(facc, pa0, vb0, facc);
            wmma::mma_sync(facc, pa0, vb1, facc);
            wmma::mma_sync(facc, pa1, vb0, facc);
        }
        if (ch + 1 < NCH64) conv_p(ch + 1);
        __syncthreads();
        if (ch + 2 < NCH64) load_v(ch + 2);
    }

    // ---- reduce 4 key-tiles, split, write A planes ----
    wmma::store_matrix_sync(stg + w * 256, facc, 16, wmma::mem_row_major);
    __syncthreads();
    for (int i = tid; i < 16 * HD_; i += 512) {
        int r = i >> 6, d = i & 63;
        int nt2 = d >> 4, c = d & 15;
        float v = stg[(0 * 4 + nt2) * 256 + r * 16 + c]
                + stg[(1 * 4 + nt2) * 256 + r * 16 + c]
                + stg[(2 * 4 + nt2) * 256 + r * 16 + c]
                + stg[(3 * 4 + nt2) * 256 + r * 16 + c];
        v *= s_rcp[r];
        size_t oi = ((size_t)b * S_ + q0 + r) * D_ + h * HD_ + d;
        __nv_bfloat16 b0 = __float2bfloat16(v);
        A0[oi] = b0;
        A1[oi] = __float2bfloat16(v - __bfloat162float(b0));
    }
}

// ---------------- launcher ----------------
extern "C" void kernel_launch(void* const* d_in, const int* in_sizes, int n_in,
                              void* d_out, int out_size)
{
    const float* X  = (const float*)d_in[0];
    const float* Wq = (const float*)d_in[1];
    const float* bq = (const float*)d_in[2];
    const float* Wk = (const float*)d_in[3];
    const float* bk = (const float*)d_in[4];
    const float* Wv = (const float*)d_in[5];
    const float* bv = (const float*)d_in[6];
    const float* Wo = (const float*)d_in[7];
    const float* bo = (const float*)d_in[8];

    static float *Qd = nullptr;
    static __nv_bfloat16 *X3[3], *K3[3], *V2[2], *A3[2], *W3[3];
    static bool init_done = false;
    if (!init_done) {
        cudaGetSymbolAddress((void**)&Qd, g_Q);
        __nv_bfloat16* base;
        cudaGetSymbolAddress((void**)&base, g_X3);
        for (int p = 0; p < 3; p++) X3[p] = base + (size_t)p * MROWS * D_;
        cudaGetSymbolAddress((void**)&base, g_K3);
        for (int p = 0; p < 3; p++) K3[p] = base + (size_t)p * MROWS * D_;
        cudaGetSymbolAddress((void**)&base, g_V2);
        for (int p = 0; p < 2; p++) V2[p] = base + (size_t)p * MROWS * D_;
        cudaGetSymbolAddress((void**)&base, g_A3);
        for (int p = 0; p < 2; p++) A3[p] = base + (size_t)p * MROWS * D_;
        cudaGetSymbolAddress((void**)&base, g_W3);
        for (int p = 0; p < 3; p++) W3[p] = base + (size_t)p * D_ * D_;
        cudaFuncSetAttribute(attn_tc,
                             cudaFuncAttributeMaxDynamicSharedMemorySize, AT_SMEM);
        cudaFuncSetAttribute(gemm_pipe<3>,
                             cudaFuncAttributeMaxDynamicSharedMemorySize, GEMM_SMEM_3);
        cudaFuncSetAttribute(gemm_pipe<2>,
                             cudaFuncAttributeMaxDynamicSharedMemorySize, GEMM_SMEM_2);
        init_done = true;
    }

    const int NX4 = MROWS * D_ / 4;
    const int NW4 = D_ * D_ / 4;
    dim3 ggrid(D_ / 128, MROWS / 128);

    split3_kernel<<<NX4 / 256, 256>>>(X, X3[0], X3[1], X3[2], NX4);

    // Q: fp32 head layout (mode 1)
    split3_kernel<<<NW4 / 256, 256>>>(Wq, W3[0], W3[1], W3[2], NW4);
    gemm_pipe<3><<<ggrid, 256, GEMM_SMEM_3>>>(X3[0], X3[1], X3[2],
        W3[0], W3[1], W3[2], bq, Qd, nullptr, nullptr, nullptr, 1);
    // K: 3-plane bf16 head layout (mode 2)
    split3_kernel<<<NW4 / 256, 256>>>(Wk, W3[0], W3[1], W3[2], NW4);
    gemm_pipe<3><<<ggrid, 256, GEMM_SMEM_3>>>(X3[0], X3[1], X3[2],
        W3[0], W3[1], W3[2], bk, nullptr, K3[0], K3[1], K3[2], 2);
    // V: 2-plane bf16 head layout (mode 3)
    split3_kernel<<<NW4 / 256, 256>>>(Wv, W3[0], W3[1], nullptr, NW4);
    gemm_pipe<2><<<ggrid, 256, GEMM_SMEM_2>>>(X3[0], X3[1], nullptr,
        W3[0], W3[1], nullptr, bv, nullptr, V2[0], V2[1], nullptr, 3);

    attn_tc<<<dim3(S_ / 16, H_, B_), 512, AT_SMEM>>>(
        Qd, K3[0], K3[1], K3[2], V2[0], V2[1], A3[0], A3[1]);

    // O: fp32 output (mode 0)
    split3_kernel<<<NW4 / 256, 256>>>(Wo, W3[0], W3[1], nullptr, NW4);
    gemm_pipe<2><<<ggrid, 256, GEMM_SMEM_2>>>(A3[0], A3[1], nullptr,
        W3[0], W3[1], nullptr, bo, (float*)d_out, nullptr, nullptr, nullptr, 0);
}